// round 14
// baseline (speedup 1.0000x reference)
#include <cuda_runtime.h>
#include <cuda_bf16.h>
#include <cuda_fp16.h>
#include <cstdint>

#define S 4096
#define HH 64
#define WW 64

// ---------------- scratch (no allocations allowed) ----------------
__device__ float g_hqkv[4 * 96 * S];
__device__ float g_mkv [4 * 64 * S];
__device__ float g_Z2  [4 * 64 * S];
__device__ float g_Zp  [4 * 32 * S];
__device__ float g_conv[4 * 192 * S];
__device__ uint32_t g_kp[4 * 2 * 65536];   // [n][att][key][dp16 perm] bf16x2
__device__ uint32_t g_vp[4 * 2 * 65536];   // [n][att][d32][kp2048 perm] f16x2

// ---------------- helpers ----------------
__device__ __forceinline__ uint32_t smem_u32(const void* p) {
    uint32_t a;
    asm("{ .reg .u64 t; cvta.to.shared.u64 t, %1; cvt.u32.u64 %0, t; }" : "=r"(a) : "l"(p));
    return a;
}
__device__ __forceinline__ void cpa16(uint32_t dst, const void* src) {
    asm volatile("cp.async.cg.shared.global [%0], [%1], 16;" :: "r"(dst), "l"(src));
}
#define CP_COMMIT() asm volatile("cp.async.commit_group;" ::: "memory")
#define CP_WAIT0()  asm volatile("cp.async.wait_group 0;" ::: "memory")
#define CP_WAIT1()  asm volatile("cp.async.wait_group 1;" ::: "memory")

__device__ __forceinline__ void mma16816(float* c, const uint32_t* a, uint32_t b0, uint32_t b1) {
    asm volatile(
        "mma.sync.aligned.m16n8k16.row.col.f32.bf16.bf16.f32 "
        "{%0,%1,%2,%3}, {%4,%5,%6,%7}, {%8,%9}, {%0,%1,%2,%3};"
        : "+f"(c[0]), "+f"(c[1]), "+f"(c[2]), "+f"(c[3])
        : "r"(a[0]), "r"(a[1]), "r"(a[2]), "r"(a[3]), "r"(b0), "r"(b1));
}
__device__ __forceinline__ void mma16816h(float* c, const uint32_t* a, uint32_t b0, uint32_t b1) {
    asm volatile(
        "mma.sync.aligned.m16n8k16.row.col.f32.f16.f16.f32 "
        "{%0,%1,%2,%3}, {%4,%5,%6,%7}, {%8,%9}, {%0,%1,%2,%3};"
        : "+f"(c[0]), "+f"(c[1]), "+f"(c[2]), "+f"(c[3])
        : "r"(a[0]), "r"(a[1]), "r"(a[2]), "r"(a[3]), "r"(b0), "r"(b1));
}
__device__ __forceinline__ void mma1688t(float* c, const uint32_t* a, uint32_t b0, uint32_t b1) {
    asm volatile(
        "mma.sync.aligned.m16n8k8.row.col.f32.tf32.tf32.f32 "
        "{%0,%1,%2,%3}, {%4,%5,%6,%7}, {%8,%9}, {%0,%1,%2,%3};"
        : "+f"(c[0]), "+f"(c[1]), "+f"(c[2]), "+f"(c[3])
        : "r"(a[0]), "r"(a[1]), "r"(a[2]), "r"(a[3]), "r"(b0), "r"(b1));
}
__device__ __forceinline__ uint32_t packbf(float lo, float hi) {
    uint32_t r;
    asm("cvt.rn.bf16x2.f32 %0, %2, %1;" : "=r"(r) : "f"(lo), "f"(hi));
    return r;
}
__device__ __forceinline__ uint32_t packh(float lo, float hi) {
    uint32_t r;
    asm("cvt.rn.f16x2.f32 %0, %2, %1;" : "=r"(r) : "f"(lo), "f"(hi));
    return r;
}
__device__ __forceinline__ uint32_t h2ex2(uint32_t x) {
    uint32_t r;
    asm("ex2.approx.f16x2 %0, %1;" : "=r"(r) : "r"(x));
    return r;
}
__device__ __forceinline__ uint32_t hadd2u(uint32_t a, uint32_t b) {
    uint32_t r;
    asm("add.rn.f16x2 %0, %1, %2;" : "=r"(r) : "r"(a), "r"(b));
    return r;
}
__device__ __forceinline__ uint32_t f2tf32(float f) {
    uint32_t r;
    asm("cvt.rna.tf32.f32 %0, %1;" : "=r"(r) : "f"(f));
    return r;
}

// ---------------- K/V repack with pair-interleaved word order ----------------
// K row (16 words): d-pair dp (ks=dp>>3, t=dp&7) stored at ks*8 + (t&3)*2 + (t>>2)
//   -> fragment words (lj, lj+4) land adjacent => LDS.64 in the mainloop.
// V row: key-pair kp (chunk=kp>>5, l=kp&31, kk=l>>3, t=l&7) stored at
//   chunk*32 + kk*8 + (t&3)*2 + (t>>2).
__global__ __launch_bounds__(256)
void repack_kernel() {
    int n = blockIdx.z, att = blockIdx.y, bx = blockIdx.x;
    int t = threadIdx.x;
    const float* K = (att == 0) ? g_hqkv + (size_t)n * 96 * S + 32 * S
                                : g_mkv  + (size_t)n * 64 * S;
    const float* V = (att == 0) ? g_hqkv + (size_t)n * 96 * S + 64 * S
                                : g_mkv  + (size_t)n * 64 * S + 32 * S;
    uint32_t* Kp = g_kp + ((size_t)n * 2 + att) * 65536;
    uint32_t* Vp = g_vp + ((size_t)n * 2 + att) * 65536;
#pragma unroll
    for (int r = 0; r < 4; r++) {
        int j = bx * 1024 + r * 256 + t;
        int key = j & 4095, dp = j >> 12;
        int kt = dp >> 3, tt = dp & 7;
        int kpos = kt * 8 + (tt & 3) * 2 + (tt >> 2);
        Kp[key * 16 + kpos] = packbf(K[(size_t)(2 * dp) * S + key],
                                     K[(size_t)(2 * dp + 1) * S + key]);
        int d = j >> 11, kp = j & 2047;
        int chunk = kp >> 5, l = kp & 31, kkg = l >> 3, tv = l & 7;
        int vpos = chunk * 32 + kkg * 8 + (tv & 3) * 2 + (tv >> 2);
        float2 v2 = *(const float2*)&V[(size_t)d * S + 2 * kp];
        Vp[d * 2048 + vpos] = packh(v2.x, v2.y);
    }
}

// ---------------- 1x1 projection as tf32 GEMM (proven body, 128-wide) ----------------
#define PRJ_XS_ST 136
#define PRJ_WS_ST 40

__device__ __forceinline__ void proj_gemm_body(
    uint32_t* Xs, uint32_t* Ws2,
    const float* Xg, const float* Wg, const float* bg,
    float* outg, int s0)
{
    int tid = threadIdx.x;
    int w = tid >> 5, lane = tid & 31;
    int lq = lane >> 2, l4 = lane & 3;

    for (int i = tid; i < 64 * 128; i += 128) {
        int ci = i >> 7, sl = i & 127;
        Xs[ci * PRJ_XS_ST + sl] = f2tf32(Xg[(size_t)ci * S + s0 + sl]);
    }
    for (int i = tid; i < 32 * 64; i += 128) {
        int co = i >> 6, ci = i & 63;
        Ws2[ci * PRJ_WS_ST + co] = f2tf32(Wg[co * 64 + ci]);
    }
    __syncthreads();

    float oacc[2][4][4];
#pragma unroll
    for (int mt = 0; mt < 2; mt++)
#pragma unroll
        for (int nt = 0; nt < 4; nt++)
#pragma unroll
            for (int r = 0; r < 4; r++) oacc[mt][nt][r] = 0.f;

#pragma unroll
    for (int kb8 = 0; kb8 < 8; kb8++) {
        int kb = kb8 * 8;
        uint32_t a[2][4];
#pragma unroll
        for (int mt = 0; mt < 2; mt++) {
            int co0 = mt * 16 + lq;
            a[mt][0] = Ws2[(kb + l4) * PRJ_WS_ST + co0];
            a[mt][1] = Ws2[(kb + l4) * PRJ_WS_ST + co0 + 8];
            a[mt][2] = Ws2[(kb + l4 + 4) * PRJ_WS_ST + co0];
            a[mt][3] = Ws2[(kb + l4 + 4) * PRJ_WS_ST + co0 + 8];
        }
#pragma unroll
        for (int nt = 0; nt < 4; nt++) {
            int scol = w * 32 + nt * 8 + lq;
            uint32_t b0 = Xs[(kb + l4) * PRJ_XS_ST + scol];
            uint32_t b1 = Xs[(kb + l4 + 4) * PRJ_XS_ST + scol];
            mma1688t(oacc[0][nt], a[0], b0, b1);
            mma1688t(oacc[1][nt], a[1], b0, b1);
        }
    }

#pragma unroll
    for (int mt = 0; mt < 2; mt++) {
        int coA = mt * 16 + lq, coB = coA + 8;
        float bA = bg[coA], bB = bg[coB];
#pragma unroll
        for (int nt = 0; nt < 4; nt++) {
            int x = s0 + w * 32 + nt * 8 + 2 * l4;
            *(float2*)&outg[(size_t)coA * S + x] = make_float2(oacc[mt][nt][0] + bA, oacc[mt][nt][1] + bA);
            *(float2*)&outg[(size_t)coB * S + x] = make_float2(oacc[mt][nt][2] + bB, oacc[mt][nt][3] + bB);
        }
    }
}

__global__ __launch_bounds__(128)
void projhm_kernel(const float* __restrict__ h, const float* __restrict__ Wh,
                   const float* __restrict__ bh, float* __restrict__ hqkv,
                   const float* __restrict__ m, const float* __restrict__ Wm,
                   const float* __restrict__ bm, float* __restrict__ mkv) {
    __shared__ uint32_t Xs[64 * PRJ_XS_ST];
    __shared__ uint32_t Ws2[64 * PRJ_WS_ST];
    int n = blockIdx.z, y = blockIdx.y;
    int s0 = blockIdx.x * 128;
    if (y < 3) {
        int co0 = y * 32;
        proj_gemm_body(Xs, Ws2, h + (size_t)n * 64 * S, Wh + (size_t)co0 * 64, bh + co0,
                       hqkv + ((size_t)n * 96 + co0) * S, s0);
    } else {
        int co0 = (y - 3) * 32;
        proj_gemm_body(Xs, Ws2, m + (size_t)n * 64 * S, Wm + (size_t)co0 * 64, bm + co0,
                       mkv + ((size_t)n * 64 + co0) * S, s0);
    }
}

// ---------------- projz: 64-wide s-tiles, 256 CTAs (latency tail fix) ----------------
#define PZ_XS_ST 72
__global__ __launch_bounds__(128)
void projz_kernel(const float* __restrict__ Z2, const float* __restrict__ Wz,
                  const float* __restrict__ bz, float* __restrict__ Zp) {
    __shared__ uint32_t Xs[64 * PZ_XS_ST];
    __shared__ uint32_t Ws2[64 * PRJ_WS_ST];
    int tid = threadIdx.x;
    int w = tid >> 5, lane = tid & 31;
    int lq = lane >> 2, l4 = lane & 3;
    int n = blockIdx.z;
    int s0 = blockIdx.x * 64;
    const float* Xg = Z2 + (size_t)n * 64 * S;
    float* outg = Zp + (size_t)n * 32 * S;

    for (int i = tid; i < 64 * 64; i += 128) {
        int ci = i >> 6, sl = i & 63;
        Xs[ci * PZ_XS_ST + sl] = f2tf32(Xg[(size_t)ci * S + s0 + sl]);
    }
    for (int i = tid; i < 32 * 64; i += 128) {
        int co = i >> 6, ci = i & 63;
        Ws2[ci * PRJ_WS_ST + co] = f2tf32(Wz[co * 64 + ci]);
    }
    __syncthreads();

    float oacc[2][2][4];
#pragma unroll
    for (int mt = 0; mt < 2; mt++)
#pragma unroll
        for (int nt = 0; nt < 2; nt++)
#pragma unroll
            for (int r = 0; r < 4; r++) oacc[mt][nt][r] = 0.f;

#pragma unroll
    for (int kb8 = 0; kb8 < 8; kb8++) {
        int kb = kb8 * 8;
        uint32_t a[2][4];
#pragma unroll
        for (int mt = 0; mt < 2; mt++) {
            int co0 = mt * 16 + lq;
            a[mt][0] = Ws2[(kb + l4) * PRJ_WS_ST + co0];
            a[mt][1] = Ws2[(kb + l4) * PRJ_WS_ST + co0 + 8];
            a[mt][2] = Ws2[(kb + l4 + 4) * PRJ_WS_ST + co0];
            a[mt][3] = Ws2[(kb + l4 + 4) * PRJ_WS_ST + co0 + 8];
        }
#pragma unroll
        for (int nt = 0; nt < 2; nt++) {
            int scol = w * 16 + nt * 8 + lq;
            uint32_t b0 = Xs[(kb + l4) * PZ_XS_ST + scol];
            uint32_t b1 = Xs[(kb + l4 + 4) * PZ_XS_ST + scol];
            mma1688t(oacc[0][nt], a[0], b0, b1);
            mma1688t(oacc[1][nt], a[1], b0, b1);
        }
    }

#pragma unroll
    for (int mt = 0; mt < 2; mt++) {
        int coA = mt * 16 + lq, coB = coA + 8;
        float bA = bz[coA], bB = bz[coB];
#pragma unroll
        for (int nt = 0; nt < 2; nt++) {
            int x = s0 + w * 16 + nt * 8 + 2 * l4;
            *(float2*)&outg[(size_t)coA * S + x] = make_float2(oacc[mt][nt][0] + bA, oacc[mt][nt][1] + bA);
            *(float2*)&outg[(size_t)coB * S + x] = make_float2(oacc[mt][nt][2] + bB, oacc[mt][nt][3] + bB);
        }
    }
}

// ---------------- flash attention: 3-buffer cp.async ring, 1 sync/chunk, LDS.64 ----------------
// smem words: Qs 2560 | Kbuf[3] 1280 ea | Vbuf[3] 1152 ea   (total 9856 w = 39.4 KB)
#define AQ_W   2560
#define AK_W   1280
#define AV_W   1152
#define A_TOT  (AQ_W + 3 * AK_W + 3 * AV_W)

__global__ __launch_bounds__(128)
void attn_mma_kernel(const float* __restrict__ hqkv, float* __restrict__ Z2) {
    __shared__ uint32_t smw[A_TOT];
    uint32_t* Qsw = smw;
    uint32_t* Kb[3] = {smw + AQ_W, smw + AQ_W + AK_W, smw + AQ_W + 2 * AK_W};
    uint32_t* Vb[3] = {smw + AQ_W + 3 * AK_W, smw + AQ_W + 3 * AK_W + AV_W,
                       smw + AQ_W + 3 * AK_W + 2 * AV_W};
    __nv_bfloat16* Qh = (__nv_bfloat16*)Qsw;

    int tid = threadIdx.x;
    int w = tid >> 5, lane = tid & 31;
    int lq = lane >> 2, lj = lane & 3;
    int n = blockIdx.z, att = blockIdx.y;
    int q0 = blockIdx.x * 128;

    const float* Q = hqkv + (size_t)n * 96 * S;
    const uint32_t* Kp = g_kp + ((size_t)n * 2 + att) * 65536;
    const uint32_t* Vp = g_vp + ((size_t)n * 2 + att) * 65536;
    float* Out = Z2 + ((size_t)n * 64 + att * 32) * S;

    uint32_t kb_a[3] = {smem_u32(Kb[0]), smem_u32(Kb[1]), smem_u32(Kb[2])};
    uint32_t vb_a[3] = {smem_u32(Vb[0]), smem_u32(Vb[1]), smem_u32(Vb[2])};

    int skey = tid >> 1, sqh = tid & 1;          // K: 2 x 16B per thread
    int svd = tid >> 2, svq = tid & 3;           // V: 2 x 16B per thread
    uint32_t kdst_off = (skey * 20 + sqh * 8) * 4;
    uint32_t vdst_off = (svd * 36 + svq * 8) * 4;

    const float scale = 0.17677669529663687f * 1.4426950408889634f;  // log2e/sqrt(32)
    for (int i = tid; i < 4096; i += 128) {
        int d = i >> 7, q = i & 127;
        Qh[q * 40 + d] = __float2bfloat16(Q[(size_t)d * S + q0 + q] * scale);
    }
    __syncthreads();

    uint32_t qa[2][2][4];
#pragma unroll
    for (int mt = 0; mt < 2; mt++) {
        int r0 = 32 * w + 16 * mt + lq;
#pragma unroll
        for (int ks = 0; ks < 2; ks++) {
            qa[mt][ks][0] = Qsw[r0 * 20 + ks * 8 + lj];
            qa[mt][ks][1] = Qsw[(r0 + 8) * 20 + ks * 8 + lj];
            qa[mt][ks][2] = Qsw[r0 * 20 + ks * 8 + lj + 4];
            qa[mt][ks][3] = Qsw[(r0 + 8) * 20 + ks * 8 + lj + 4];
        }
    }

    float oacc[2][4][4];
#pragma unroll
    for (int mt = 0; mt < 2; mt++)
#pragma unroll
        for (int nt = 0; nt < 4; nt++)
#pragma unroll
            for (int r = 0; r < 4; r++) oacc[mt][nt][r] = 0.f;
    float l_acc[4] = {0.f, 0.f, 0.f, 0.f};

    auto stageA = [&](int kt, int bsel) {
        const uint32_t* ksrc = Kp + ((size_t)(kt * 64 + skey)) * 16 + sqh * 8;
        uint32_t kdst = kb_a[bsel] + kdst_off;
        cpa16(kdst, ksrc);
        cpa16(kdst + 16, ksrc + 4);
        const uint32_t* vsrc = Vp + (size_t)svd * 2048 + kt * 32 + svq * 8;
        uint32_t vdst = vb_a[bsel] + vdst_off;
        cpa16(vdst, vsrc);
        cpa16(vdst + 16, vsrc + 4);
        CP_COMMIT();
    };

    stageA(0, 0);
    stageA(1, 1);

#pragma unroll 1
    for (int kt = 0; kt < 64; kt++) {
        if (kt < 63) CP_WAIT1(); else CP_WAIT0();
        __syncthreads();                         // publishes chunk kt; proves kt-1 compute done
        if (kt < 62) stageA(kt + 2, (kt + 2) % 3);

        const uint32_t* Kbuf = Kb[kt % 3];
        const uint32_t* Vbuf = Vb[kt % 3];

        uint32_t rsh[2][2] = {{0u, 0u}, {0u, 0u}};
#pragma unroll
        for (int kk = 0; kk < 4; kk++) {
            uint32_t p[2][4];
#pragma unroll
            for (int half = 0; half < 2; half++) {
                int nn = kk * 2 + half;
                float c[2][4];
#pragma unroll
                for (int mt = 0; mt < 2; mt++)
#pragma unroll
                    for (int r = 0; r < 4; r++) c[mt][r] = 0.f;
#pragma unroll
                for (int ks = 0; ks < 2; ks++) {
                    uint2 b = *(const uint2*)&Kbuf[(nn * 8 + lq) * 20 + ks * 8 + 2 * lj];
                    mma16816(c[0], qa[0][ks], b.x, b.y);
                    mma16816(c[1], qa[1][ks], b.x, b.y);
                }
#pragma unroll
                for (int mt = 0; mt < 2; mt++) {
                    uint32_t p01 = h2ex2(packh(c[mt][0], c[mt][1]));
                    uint32_t p23 = h2ex2(packh(c[mt][2], c[mt][3]));
                    rsh[mt][0] = hadd2u(rsh[mt][0], p01);
                    rsh[mt][1] = hadd2u(rsh[mt][1], p23);
                    p[mt][half * 2 + 0] = p01;
                    p[mt][half * 2 + 1] = p23;
                }
            }
#pragma unroll
            for (int nt = 0; nt < 4; nt++) {
                uint2 v = *(const uint2*)&Vbuf[(nt * 8 + lq) * 36 + kk * 8 + 2 * lj];
                mma16816h(oacc[0][nt], p[0], v.x, v.y);
                mma16816h(oacc[1][nt], p[1], v.x, v.y);
            }
        }
#pragma unroll
        for (int mt = 0; mt < 2; mt++) {
            float2 f0 = __half22float2(*(__half2*)&rsh[mt][0]);
            float2 f1 = __half22float2(*(__half2*)&rsh[mt][1]);
            float r0 = f0.x + f0.y, r1 = f1.x + f1.y;
            r0 += __shfl_xor_sync(0xffffffffu, r0, 1);
            r0 += __shfl_xor_sync(0xffffffffu, r0, 2);
            r1 += __shfl_xor_sync(0xffffffffu, r1, 1);
            r1 += __shfl_xor_sync(0xffffffffu, r1, 2);
            l_acc[mt * 2 + 0] += r0;
            l_acc[mt * 2 + 1] += r1;
        }
    }

    // ---- epilogue: normalize, stage Osm[d][q] stride 130, coalesced store
    __syncthreads();
    float* Osm = (float*)smw;
    float inv[4];
#pragma unroll
    for (int r = 0; r < 4; r++) inv[r] = 1.0f / l_acc[r];
#pragma unroll
    for (int mt = 0; mt < 2; mt++) {
        int r0 = 32 * w + 16 * mt + lq;
#pragma unroll
        for (int nt = 0; nt < 4; nt++) {
            int d0 = nt * 8 + 2 * lj;
            Osm[(d0 + 0) * 130 + r0]     = oacc[mt][nt][0] * inv[mt * 2];
            Osm[(d0 + 1) * 130 + r0]     = oacc[mt][nt][1] * inv[mt * 2];
            Osm[(d0 + 0) * 130 + r0 + 8] = oacc[mt][nt][2] * inv[mt * 2 + 1];
            Osm[(d0 + 1) * 130 + r0 + 8] = oacc[mt][nt][3] * inv[mt * 2 + 1];
        }
    }
    __syncthreads();
    for (int i = tid; i < 4096; i += 128) {
        int d = i >> 7, q = i & 127;
        Out[(size_t)d * S + q0 + q] = Osm[d * 130 + q];
    }
}

// ---------------- 3x3 conv implicit GEMM (round-10 proven, unchanged) ----------------
__global__ __launch_bounds__(256)
void conv_tc_kernel(const float* __restrict__ Zin, const float* __restrict__ hin,
                    const float* __restrict__ Wo, const float* __restrict__ bo,
                    float* __restrict__ out) {
    __shared__ uint32_t patchF[16 * 332];
    __shared__ uint4 Wfrag[18 * 2 * 32];

    int tid = threadIdx.x;
    int w = tid >> 5, lane = tid & 31;
    int lq = lane >> 2, l4 = lane & 3;
    int n = blockIdx.z, cog = blockIdx.y, tile = blockIdx.x;
    int ty0 = (tile >> 2) * 16, tx0 = (tile & 3) * 16;

    int pos0 = tid;
    int yy0 = pos0 / 18 + ty0 - 1, xx0 = pos0 % 18 + tx0 - 1;
    bool va0 = (yy0 >= 0 && yy0 < HH && xx0 >= 0 && xx0 < WW);
    int g0 = yy0 * WW + xx0;
    int pos1 = tid + 256;
    bool has1 = pos1 < 324;
    int yy1 = pos1 / 18 + ty0 - 1, xx1 = pos1 % 18 + tx0 - 1;
    bool va1 = has1 && (yy1 >= 0 && yy1 < HH && xx1 >= 0 && xx1 < WW);
    int g1 = yy1 * WW + xx1;

    const uint32_t* rowA = patchF + l4 * 332;
    const uint32_t* rowB = patchF + (8 + l4) * 332;
    int bbase[4];
#pragma unroll
    for (int nt = 0; nt < 4; nt++)
        bbase[nt] = (2 * w + (nt >> 1)) * 18 + (nt & 1) * 8 + lq;

    float oacc[2][4][4];
#pragma unroll
    for (int mt = 0; mt < 2; mt++)
#pragma unroll
        for (int nt = 0; nt < 4; nt++)
#pragma unroll
            for (int r = 0; r < 4; r++) oacc[mt][nt][r] = 0.f;

#pragma unroll 1
    for (int cig = 0; cig < 6; cig++) {
        const float* base = (cig < 2)
            ? Zin + ((size_t)n * 32 + cig * 16) * S
            : hin + ((size_t)n * 64 + (cig * 16 - 32)) * S;
        __syncthreads();
#pragma unroll
        for (int ci = 0; ci < 16; ci++)
            patchF[ci * 332 + pos0] = va0 ? f2tf32(base[(size_t)ci * S + g0]) : 0u;
        if (has1) {
#pragma unroll
            for (int ci = 0; ci < 16; ci++)
                patchF[ci * 332 + pos1] = va1 ? f2tf32(base[(size_t)ci * S + g1]) : 0u;
        }
        for (int i = tid; i < 1152; i += 256) {
            int ln = i & 31, mtc = i >> 5;
            int mt = mtc & 1, chunk = mtc >> 1;
            int khkw = chunk >> 1, c8 = chunk & 1;
            int ciL = c8 * 8 + (ln & 3);
            int co0 = mt * 16 + (ln >> 2);
            const float* wp = Wo + (((size_t)cog * 32 + co0) * 96 + cig * 16 + ciL) * 9 + khkw;
            Wfrag[i] = make_uint4(f2tf32(wp[0]), f2tf32(wp[8 * 864]),
                                  f2tf32(wp[36]), f2tf32(wp[8 * 864 + 36]));
        }
        __syncthreads();

#pragma unroll
        for (int khkw = 0; khkw < 9; khkw++) {
            int kh = khkw / 3, kw = khkw % 3;
#pragma unroll
            for (int c8 = 0; c8 < 2; c8++) {
                int chunk = khkw * 2 + c8;
                uint4 a0 = Wfrag[(chunk * 2 + 0) * 32 + lane];
                uint4 a1 = Wfrag[(chunk * 2 + 1) * 32 + lane];
                const uint32_t* rr = c8 ? rowB : rowA;
#pragma unroll
                for (int nt = 0; nt < 4; nt++) {
                    int off = bbase[nt] + kh * 18 + kw;
                    uint32_t b0 = rr[off];
                    uint32_t b1 = rr[4 * 332 + off];
                    mma1688t(oacc[0][nt], (const uint32_t*)&a0, b0, b1);
                    mma1688t(oacc[1][nt], (const uint32_t*)&a1, b0, b1);
                }
            }
        }
    }

#pragma unroll
    for (int mt = 0; mt < 2; mt++) {
        int coA = cog * 32 + mt * 16 + lq;
        int coB = coA + 8;
        float bA = bo[coA], bB = bo[coB];
        size_t baseA = ((size_t)n * 192 + coA) * S;
        size_t baseB = ((size_t)n * 192 + coB) * S;
#pragma unroll
        for (int nt = 0; nt < 4; nt++) {
            int y = ty0 + 2 * w + (nt >> 1);
            int x = tx0 + (nt & 1) * 8 + 2 * l4;
            *(float2*)&out[baseA + y * WW + x] = make_float2(oacc[mt][nt][0] + bA, oacc[mt][nt][1] + bA);
            *(float2*)&out[baseB + y * WW + x] = make_float2(oacc[mt][nt][2] + bB, oacc[mt][nt][3] + bB);
        }
    }
}

// ---------------- gates (float4) ----------------
__global__ __launch_bounds__(256)
void gates_kernel(const float* __restrict__ conv, const float* __restrict__ m,
                  float* __restrict__ out) {
    int idx4 = blockIdx.x * 256 + threadIdx.x;
    int n = idx4 >> 16;
    int rem = (idx4 & 65535) * 4;
    size_t base = (size_t)n * 192 * S;
    float4 iv = *(const float4*)&conv[base + rem];
    float4 gv = *(const float4*)&conv[base + 64 * S + rem];
    float4 ov = *(const float4*)&conv[base + 128 * S + rem];
    float4 mi = *(const float4*)&m[(size_t)n * 64 * S + rem];
    float4 hn, mn;
    {
        float si = 1.0f / (1.0f + __expf(-iv.x)), gg = tanhf(gv.x), so = 1.0f / (1.0f + __expf(-ov.x));
        mn.x = si * gg + (1.0f - si) * mi.x; hn.x = so * mn.x;
        si = 1.0f / (1.0f + __expf(-iv.y)); gg = tanhf(gv.y); so = 1.0f / (1.0f + __expf(-ov.y));
        mn.y = si * gg + (1.0f - si) * mi.y; hn.y = so * mn.y;
        si = 1.0f / (1.0f + __expf(-iv.z)); gg = tanhf(gv.z); so = 1.0f / (1.0f + __expf(-ov.z));
        mn.z = si * gg + (1.0f - si) * mi.z; hn.z = so * mn.z;
        si = 1.0f / (1.0f + __expf(-iv.w)); gg = tanhf(gv.w); so = 1.0f / (1.0f + __expf(-ov.w));
        mn.w = si * gg + (1.0f - si) * mi.w; hn.w = so * mn.w;
    }
    size_t oidx = (size_t)n * 64 * S + rem;
    *(float4*)&out[oidx] = hn;
    *(float4*)&out[1048576 + oidx] = mn;
}

// ---------------- launch ----------------
extern "C" void kernel_launch(void* const* d_in, const int* in_sizes, int n_in,
                              void* d_out, int out_size) {
    const float* h  = (const float*)d_in[0];
    const float* m  = (const float*)d_in[1];
    const float* Wh = (const float*)d_in[2];
    const float* bh = (const float*)d_in[3];
    const float* Wm = (const float*)d_in[4];
    const float* bm = (const float*)d_in[5];
    const float* Wz = (const float*)d_in[6];
    const float* bz = (const float*)d_in[7];
    const float* Wo = (const float*)d_in[8];
    const float* bo = (const float*)d_in[9];
    float* out = (float*)d_out;

    float *pHqkv, *pMkv, *pZ2, *pZp, *pConv;
    cudaGetSymbolAddress((void**)&pHqkv, g_hqkv);
    cudaGetSymbolAddress((void**)&pMkv,  g_mkv);
    cudaGetSymbolAddress((void**)&pZ2,   g_Z2);
    cudaGetSymbolAddress((void**)&pZp,   g_Zp);
    cudaGetSymbolAddress((void**)&pConv, g_conv);

    projhm_kernel<<<dim3(32, 5, 4), 128>>>(h, Wh, bh, pHqkv, m, Wm, bm, pMkv);
    repack_kernel<<<dim3(64, 2, 4), 256>>>();
    attn_mma_kernel<<<dim3(32, 2, 4), 128>>>(pHqkv, pZ2);
    projz_kernel<<<dim3(64, 1, 4), 128>>>(pZ2, Wz, bz, pZp);
    conv_tc_kernel<<<dim3(16, 6, 4), 256>>>(pZp, h, Wo, bo, pConv);
    gates_kernel<<<1024, 256>>>(pConv, m, out);
}

// round 15
// speedup vs baseline: 1.1044x; 1.1044x over previous
#include <cuda_runtime.h>
#include <cuda_bf16.h>
#include <cuda_fp16.h>
#include <cstdint>

#define S 4096
#define HH 64
#define WW 64

// ---------------- scratch (no allocations allowed) ----------------
__device__ float g_hqkv[4 * 96 * S];
__device__ float g_mkv [4 * 64 * S];
__device__ float g_Z2  [4 * 64 * S];
__device__ float g_Zp  [4 * 32 * S];
__device__ float g_conv[4 * 192 * S];
__device__ uint32_t g_kp[4 * 2 * 65536];   // [n][att][key][dp16] bf16x2
__device__ uint32_t g_vp[4 * 2 * 65536];   // [n][att][d32][kp2048] f16x2

// ---------------- helpers ----------------
__device__ __forceinline__ uint32_t smem_u32(const void* p) {
    uint32_t a;
    asm("{ .reg .u64 t; cvta.to.shared.u64 t, %1; cvt.u32.u64 %0, t; }" : "=r"(a) : "l"(p));
    return a;
}
__device__ __forceinline__ void cpa16(uint32_t dst, const void* src) {
    asm volatile("cp.async.cg.shared.global [%0], [%1], 16;" :: "r"(dst), "l"(src));
}
#define CP_COMMIT() asm volatile("cp.async.commit_group;" ::: "memory")
#define CP_WAIT0()  asm volatile("cp.async.wait_group 0;" ::: "memory")
#define CP_WAIT1()  asm volatile("cp.async.wait_group 1;" ::: "memory")

__device__ __forceinline__ void mma16816(float* c, const uint32_t* a, uint32_t b0, uint32_t b1) {
    asm volatile(
        "mma.sync.aligned.m16n8k16.row.col.f32.bf16.bf16.f32 "
        "{%0,%1,%2,%3}, {%4,%5,%6,%7}, {%8,%9}, {%0,%1,%2,%3};"
        : "+f"(c[0]), "+f"(c[1]), "+f"(c[2]), "+f"(c[3])
        : "r"(a[0]), "r"(a[1]), "r"(a[2]), "r"(a[3]), "r"(b0), "r"(b1));
}
__device__ __forceinline__ void mma16816h(float* c, const uint32_t* a, uint32_t b0, uint32_t b1) {
    asm volatile(
        "mma.sync.aligned.m16n8k16.row.col.f32.f16.f16.f32 "
        "{%0,%1,%2,%3}, {%4,%5,%6,%7}, {%8,%9}, {%0,%1,%2,%3};"
        : "+f"(c[0]), "+f"(c[1]), "+f"(c[2]), "+f"(c[3])
        : "r"(a[0]), "r"(a[1]), "r"(a[2]), "r"(a[3]), "r"(b0), "r"(b1));
}
__device__ __forceinline__ void mma1688t(float* c, const uint32_t* a, uint32_t b0, uint32_t b1) {
    asm volatile(
        "mma.sync.aligned.m16n8k8.row.col.f32.tf32.tf32.f32 "
        "{%0,%1,%2,%3}, {%4,%5,%6,%7}, {%8,%9}, {%0,%1,%2,%3};"
        : "+f"(c[0]), "+f"(c[1]), "+f"(c[2]), "+f"(c[3])
        : "r"(a[0]), "r"(a[1]), "r"(a[2]), "r"(a[3]), "r"(b0), "r"(b1));
}
__device__ __forceinline__ uint32_t packbf(float lo, float hi) {
    uint32_t r;
    asm("cvt.rn.bf16x2.f32 %0, %2, %1;" : "=r"(r) : "f"(lo), "f"(hi));
    return r;
}
__device__ __forceinline__ uint32_t packh(float lo, float hi) {
    uint32_t r;
    asm("cvt.rn.f16x2.f32 %0, %2, %1;" : "=r"(r) : "f"(lo), "f"(hi));
    return r;
}
__device__ __forceinline__ uint32_t h2ex2(uint32_t x) {
    uint32_t r;
    asm("ex2.approx.f16x2 %0, %1;" : "=r"(r) : "r"(x));
    return r;
}
__device__ __forceinline__ uint32_t hadd2u(uint32_t a, uint32_t b) {
    uint32_t r;
    asm("add.rn.f16x2 %0, %1, %2;" : "=r"(r) : "r"(a), "r"(b));
    return r;
}
__device__ __forceinline__ uint32_t f2tf32(float f) {
    uint32_t r;
    asm("cvt.rna.tf32.f32 %0, %1;" : "=r"(r) : "f"(f));
    return r;
}

// ---------------- K/V repack (round-13 proven layout) ----------------
__global__ __launch_bounds__(256)
void repack_kernel() {
    int n = blockIdx.z, att = blockIdx.y, bx = blockIdx.x;
    int t = threadIdx.x;
    const float* K = (att == 0) ? g_hqkv + (size_t)n * 96 * S + 32 * S
                                : g_mkv  + (size_t)n * 64 * S;
    const float* V = (att == 0) ? g_hqkv + (size_t)n * 96 * S + 64 * S
                                : g_mkv  + (size_t)n * 64 * S + 32 * S;
    uint32_t* Kp = g_kp + ((size_t)n * 2 + att) * 65536;
    uint32_t* Vp = g_vp + ((size_t)n * 2 + att) * 65536;
#pragma unroll
    for (int r = 0; r < 4; r++) {
        int j = bx * 1024 + r * 256 + t;
        int key = j & 4095, dp = j >> 12;
        Kp[key * 16 + dp] = packbf(K[(size_t)(2 * dp) * S + key],
                                   K[(size_t)(2 * dp + 1) * S + key]);
        int d = j >> 11, kp = j & 2047;
        float2 v2 = *(const float2*)&V[(size_t)d * S + 2 * kp];
        Vp[d * 2048 + kp] = packh(v2.x, v2.y);
    }
}

// ---------------- 1x1 projection as tf32 GEMM (proven body) ----------------
#define PRJ_XS_ST 136
#define PRJ_WS_ST 40

__device__ __forceinline__ void proj_gemm_body(
    uint32_t* Xs, uint32_t* Ws2,
    const float* Xg, const float* Wg, const float* bg,
    float* outg, int s0)
{
    int tid = threadIdx.x;
    int w = tid >> 5, lane = tid & 31;
    int lq = lane >> 2, l4 = lane & 3;

    for (int i = tid; i < 64 * 128; i += 128) {
        int ci = i >> 7, sl = i & 127;
        Xs[ci * PRJ_XS_ST + sl] = f2tf32(Xg[(size_t)ci * S + s0 + sl]);
    }
    for (int i = tid; i < 32 * 64; i += 128) {
        int co = i >> 6, ci = i & 63;
        Ws2[ci * PRJ_WS_ST + co] = f2tf32(Wg[co * 64 + ci]);
    }
    __syncthreads();

    float oacc[2][4][4];
#pragma unroll
    for (int mt = 0; mt < 2; mt++)
#pragma unroll
        for (int nt = 0; nt < 4; nt++)
#pragma unroll
            for (int r = 0; r < 4; r++) oacc[mt][nt][r] = 0.f;

#pragma unroll
    for (int kb8 = 0; kb8 < 8; kb8++) {
        int kb = kb8 * 8;
        uint32_t a[2][4];
#pragma unroll
        for (int mt = 0; mt < 2; mt++) {
            int co0 = mt * 16 + lq;
            a[mt][0] = Ws2[(kb + l4) * PRJ_WS_ST + co0];
            a[mt][1] = Ws2[(kb + l4) * PRJ_WS_ST + co0 + 8];
            a[mt][2] = Ws2[(kb + l4 + 4) * PRJ_WS_ST + co0];
            a[mt][3] = Ws2[(kb + l4 + 4) * PRJ_WS_ST + co0 + 8];
        }
#pragma unroll
        for (int nt = 0; nt < 4; nt++) {
            int scol = w * 32 + nt * 8 + lq;
            uint32_t b0 = Xs[(kb + l4) * PRJ_XS_ST + scol];
            uint32_t b1 = Xs[(kb + l4 + 4) * PRJ_XS_ST + scol];
            mma1688t(oacc[0][nt], a[0], b0, b1);
            mma1688t(oacc[1][nt], a[1], b0, b1);
        }
    }

#pragma unroll
    for (int mt = 0; mt < 2; mt++) {
        int coA = mt * 16 + lq, coB = coA + 8;
        float bA = bg[coA], bB = bg[coB];
#pragma unroll
        for (int nt = 0; nt < 4; nt++) {
            int x = s0 + w * 32 + nt * 8 + 2 * l4;
            *(float2*)&outg[(size_t)coA * S + x] = make_float2(oacc[mt][nt][0] + bA, oacc[mt][nt][1] + bA);
            *(float2*)&outg[(size_t)coB * S + x] = make_float2(oacc[mt][nt][2] + bB, oacc[mt][nt][3] + bB);
        }
    }
}

__global__ __launch_bounds__(128)
void projhm_kernel(const float* __restrict__ h, const float* __restrict__ Wh,
                   const float* __restrict__ bh, float* __restrict__ hqkv,
                   const float* __restrict__ m, const float* __restrict__ Wm,
                   const float* __restrict__ bm, float* __restrict__ mkv) {
    __shared__ uint32_t Xs[64 * PRJ_XS_ST];
    __shared__ uint32_t Ws2[64 * PRJ_WS_ST];
    int n = blockIdx.z, y = blockIdx.y;
    int s0 = blockIdx.x * 128;
    if (y < 3) {
        int co0 = y * 32;
        proj_gemm_body(Xs, Ws2, h + (size_t)n * 64 * S, Wh + (size_t)co0 * 64, bh + co0,
                       hqkv + ((size_t)n * 96 + co0) * S, s0);
    } else {
        int co0 = (y - 3) * 32;
        proj_gemm_body(Xs, Ws2, m + (size_t)n * 64 * S, Wm + (size_t)co0 * 64, bm + co0,
                       mkv + ((size_t)n * 64 + co0) * S, s0);
    }
}

// ---------------- projz: 64-wide s-tiles, 256 CTAs (round-14 proven) ----------------
#define PZ_XS_ST 72
__global__ __launch_bounds__(128)
void projz_kernel(const float* __restrict__ Z2, const float* __restrict__ Wz,
                  const float* __restrict__ bz, float* __restrict__ Zp) {
    __shared__ uint32_t Xs[64 * PZ_XS_ST];
    __shared__ uint32_t Ws2[64 * PRJ_WS_ST];
    int tid = threadIdx.x;
    int w = tid >> 5, lane = tid & 31;
    int lq = lane >> 2, l4 = lane & 3;
    int n = blockIdx.z;
    int s0 = blockIdx.x * 64;
    const float* Xg = Z2 + (size_t)n * 64 * S;
    float* outg = Zp + (size_t)n * 32 * S;

    for (int i = tid; i < 64 * 64; i += 128) {
        int ci = i >> 6, sl = i & 63;
        Xs[ci * PZ_XS_ST + sl] = f2tf32(Xg[(size_t)ci * S + s0 + sl]);
    }
    for (int i = tid; i < 32 * 64; i += 128) {
        int co = i >> 6, ci = i & 63;
        Ws2[ci * PRJ_WS_ST + co] = f2tf32(Wz[co * 64 + ci]);
    }
    __syncthreads();

    float oacc[2][2][4];
#pragma unroll
    for (int mt = 0; mt < 2; mt++)
#pragma unroll
        for (int nt = 0; nt < 2; nt++)
#pragma unroll
            for (int r = 0; r < 4; r++) oacc[mt][nt][r] = 0.f;

#pragma unroll
    for (int kb8 = 0; kb8 < 8; kb8++) {
        int kb = kb8 * 8;
        uint32_t a[2][4];
#pragma unroll
        for (int mt = 0; mt < 2; mt++) {
            int co0 = mt * 16 + lq;
            a[mt][0] = Ws2[(kb + l4) * PRJ_WS_ST + co0];
            a[mt][1] = Ws2[(kb + l4) * PRJ_WS_ST + co0 + 8];
            a[mt][2] = Ws2[(kb + l4 + 4) * PRJ_WS_ST + co0];
            a[mt][3] = Ws2[(kb + l4 + 4) * PRJ_WS_ST + co0 + 8];
        }
#pragma unroll
        for (int nt = 0; nt < 2; nt++) {
            int scol = w * 16 + nt * 8 + lq;
            uint32_t b0 = Xs[(kb + l4) * PZ_XS_ST + scol];
            uint32_t b1 = Xs[(kb + l4 + 4) * PZ_XS_ST + scol];
            mma1688t(oacc[0][nt], a[0], b0, b1);
            mma1688t(oacc[1][nt], a[1], b0, b1);
        }
    }

#pragma unroll
    for (int mt = 0; mt < 2; mt++) {
        int coA = mt * 16 + lq, coB = coA + 8;
        float bA = bz[coA], bB = bz[coB];
#pragma unroll
        for (int nt = 0; nt < 2; nt++) {
            int x = s0 + w * 16 + nt * 8 + 2 * l4;
            *(float2*)&outg[(size_t)coA * S + x] = make_float2(oacc[mt][nt][0] + bA, oacc[mt][nt][1] + bA);
            *(float2*)&outg[(size_t)coB * S + x] = make_float2(oacc[mt][nt][2] + bB, oacc[mt][nt][3] + bB);
        }
    }
}

// ---------------- flash attention (round-13 proven: 2-buffer cp.async) ----------------
#define AQ_W   2560
#define AK_W   1280
#define AV_W   1152
#define A_TOT  (AQ_W + 2 * AK_W + 2 * AV_W)

__global__ __launch_bounds__(128)
void attn_mma_kernel(const float* __restrict__ hqkv, float* __restrict__ Z2) {
    __shared__ uint32_t smw[A_TOT];
    uint32_t* Qsw = smw;
    uint32_t* Kb0 = smw + AQ_W;
    uint32_t* Vb0 = smw + AQ_W + 2 * AK_W;
    __nv_bfloat16* Qh = (__nv_bfloat16*)Qsw;

    int tid = threadIdx.x;
    int w = tid >> 5, lane = tid & 31;
    int lq = lane >> 2, lj = lane & 3;
    int n = blockIdx.z, att = blockIdx.y;
    int q0 = blockIdx.x * 128;

    const float* Q = hqkv + (size_t)n * 96 * S;
    const uint32_t* Kp = g_kp + ((size_t)n * 2 + att) * 65536;
    const uint32_t* Vp = g_vp + ((size_t)n * 2 + att) * 65536;
    float* Out = Z2 + ((size_t)n * 64 + att * 32) * S;

    uint32_t kb_a[2] = {smem_u32(Kb0), smem_u32(Kb0 + AK_W)};
    uint32_t vb_a[2] = {smem_u32(Vb0), smem_u32(Vb0 + AV_W)};

    int skey = tid >> 1, sqh = tid & 1;
    int svd = tid >> 2, svq = tid & 3;
    uint32_t kdst_off = (skey * 20 + sqh * 8) * 4;
    uint32_t vdst_off = (svd * 36 + svq * 8) * 4;

    const float scale = 0.17677669529663687f * 1.4426950408889634f;  // log2e/sqrt(32)
    for (int i = tid; i < 4096; i += 128) {
        int d = i >> 7, q = i & 127;
        Qh[q * 40 + d] = __float2bfloat16(Q[(size_t)d * S + q0 + q] * scale);
    }
    __syncthreads();

    uint32_t qa[2][2][4];
#pragma unroll
    for (int mt = 0; mt < 2; mt++) {
        int r0 = 32 * w + 16 * mt + lq;
#pragma unroll
        for (int ks = 0; ks < 2; ks++) {
            qa[mt][ks][0] = Qsw[r0 * 20 + ks * 8 + lj];
            qa[mt][ks][1] = Qsw[(r0 + 8) * 20 + ks * 8 + lj];
            qa[mt][ks][2] = Qsw[r0 * 20 + ks * 8 + lj + 4];
            qa[mt][ks][3] = Qsw[(r0 + 8) * 20 + ks * 8 + lj + 4];
        }
    }

    float oacc[2][4][4];
#pragma unroll
    for (int mt = 0; mt < 2; mt++)
#pragma unroll
        for (int nt = 0; nt < 4; nt++)
#pragma unroll
            for (int r = 0; r < 4; r++) oacc[mt][nt][r] = 0.f;
    float l_acc[4] = {0.f, 0.f, 0.f, 0.f};

    auto stageA = [&](int kt, int bsel) {
        const uint32_t* ksrc = Kp + ((size_t)(kt * 64 + skey)) * 16 + sqh * 8;
        uint32_t kdst = kb_a[bsel] + kdst_off;
        cpa16(kdst, ksrc);
        cpa16(kdst + 16, ksrc + 4);
        const uint32_t* vsrc = Vp + (size_t)svd * 2048 + kt * 32 + svq * 8;
        uint32_t vdst = vb_a[bsel] + vdst_off;
        cpa16(vdst, vsrc);
        cpa16(vdst + 16, vsrc + 4);
        CP_COMMIT();
    };

    stageA(0, 0);

#pragma unroll 1
    for (int kt = 0; kt < 64; kt++) {
        if (kt < 63) {
            stageA(kt + 1, (kt + 1) & 1);
            CP_WAIT1();
        } else {
            CP_WAIT0();
        }
        __syncthreads();

        const uint32_t* Kbuf = Kb0 + (kt & 1) * AK_W;
        const uint32_t* Vbuf = Vb0 + (kt & 1) * AV_W;

        uint32_t p[2][4][4];
        uint32_t rsh[2][2] = {{0u, 0u}, {0u, 0u}};
#pragma unroll
        for (int nn = 0; nn < 8; nn++) {
            float c[2][4];
#pragma unroll
            for (int mt = 0; mt < 2; mt++)
#pragma unroll
                for (int r = 0; r < 4; r++) c[mt][r] = 0.f;
#pragma unroll
            for (int ks = 0; ks < 2; ks++) {
                int bw = (nn * 8 + lq) * 20 + ks * 8 + lj;
                uint32_t b0 = Kbuf[bw], b1 = Kbuf[bw + 4];
                mma16816(c[0], qa[0][ks], b0, b1);
                mma16816(c[1], qa[1][ks], b0, b1);
            }
            int kk = nn >> 1, half = (nn & 1) * 2;
#pragma unroll
            for (int mt = 0; mt < 2; mt++) {
                uint32_t p01 = h2ex2(packh(c[mt][0], c[mt][1]));
                uint32_t p23 = h2ex2(packh(c[mt][2], c[mt][3]));
                rsh[mt][0] = hadd2u(rsh[mt][0], p01);
                rsh[mt][1] = hadd2u(rsh[mt][1], p23);
                p[mt][kk][half + 0] = p01;
                p[mt][kk][half + 1] = p23;
            }
        }
#pragma unroll
        for (int mt = 0; mt < 2; mt++) {
            float2 f0 = __half22float2(*(__half2*)&rsh[mt][0]);
            float2 f1 = __half22float2(*(__half2*)&rsh[mt][1]);
            float r0 = f0.x + f0.y, r1 = f1.x + f1.y;
            r0 += __shfl_xor_sync(0xffffffffu, r0, 1);
            r0 += __shfl_xor_sync(0xffffffffu, r0, 2);
            r1 += __shfl_xor_sync(0xffffffffu, r1, 1);
            r1 += __shfl_xor_sync(0xffffffffu, r1, 2);
            l_acc[mt * 2 + 0] += r0;
            l_acc[mt * 2 + 1] += r1;
        }

#pragma unroll
        for (int nt = 0; nt < 4; nt++) {
#pragma unroll
            for (int kk = 0; kk < 4; kk++) {
                int bw = (nt * 8 + lq) * 36 + kk * 8 + lj;
                uint32_t b0 = Vbuf[bw], b1 = Vbuf[bw + 4];
                mma16816h(oacc[0][nt], p[0][kk], b0, b1);
                mma16816h(oacc[1][nt], p[1][kk], b0, b1);
            }
        }
        __syncthreads();
    }

    // ---- epilogue
    float* Osm = (float*)smw;
    float inv[4];
#pragma unroll
    for (int r = 0; r < 4; r++) inv[r] = 1.0f / l_acc[r];
#pragma unroll
    for (int mt = 0; mt < 2; mt++) {
        int r0 = 32 * w + 16 * mt + lq;
#pragma unroll
        for (int nt = 0; nt < 4; nt++) {
            int d0 = nt * 8 + 2 * lj;
            Osm[(d0 + 0) * 130 + r0]     = oacc[mt][nt][0] * inv[mt * 2];
            Osm[(d0 + 1) * 130 + r0]     = oacc[mt][nt][1] * inv[mt * 2];
            Osm[(d0 + 0) * 130 + r0 + 8] = oacc[mt][nt][2] * inv[mt * 2 + 1];
            Osm[(d0 + 1) * 130 + r0 + 8] = oacc[mt][nt][3] * inv[mt * 2 + 1];
        }
    }
    __syncthreads();
    for (int i = tid; i < 4096; i += 128) {
        int d = i >> 7, q = i & 127;
        Out[(size_t)d * S + q0 + q] = Osm[d * 130 + q];
    }
}

// ---------------- 3x3 conv implicit GEMM — patch stride 328 (bank fix) ----------------
#define CPS 328
__global__ __launch_bounds__(256)
void conv_tc_kernel(const float* __restrict__ Zin, const float* __restrict__ hin,
                    const float* __restrict__ Wo, const float* __restrict__ bo,
                    float* __restrict__ out) {
    __shared__ uint32_t patchF[16 * CPS];
    __shared__ uint4 Wfrag[18 * 2 * 32];

    int tid = threadIdx.x;
    int w = tid >> 5, lane = tid & 31;
    int lq = lane >> 2, l4 = lane & 3;
    int n = blockIdx.z, cog = blockIdx.y, tile = blockIdx.x;
    int ty0 = (tile >> 2) * 16, tx0 = (tile & 3) * 16;

    int pos0 = tid;
    int yy0 = pos0 / 18 + ty0 - 1, xx0 = pos0 % 18 + tx0 - 1;
    bool va0 = (yy0 >= 0 && yy0 < HH && xx0 >= 0 && xx0 < WW);
    int g0 = yy0 * WW + xx0;
    int pos1 = tid + 256;
    bool has1 = pos1 < 324;
    int yy1 = pos1 / 18 + ty0 - 1, xx1 = pos1 % 18 + tx0 - 1;
    bool va1 = has1 && (yy1 >= 0 && yy1 < HH && xx1 >= 0 && xx1 < WW);
    int g1 = yy1 * WW + xx1;

    const uint32_t* rowA = patchF + l4 * CPS;
    const uint32_t* rowB = patchF + (8 + l4) * CPS;
    int bbase[4];
#pragma unroll
    for (int nt = 0; nt < 4; nt++)
        bbase[nt] = (2 * w + (nt >> 1)) * 18 + (nt & 1) * 8 + lq;

    float oacc[2][4][4];
#pragma unroll
    for (int mt = 0; mt < 2; mt++)
#pragma unroll
        for (int nt = 0; nt < 4; nt++)
#pragma unroll
            for (int r = 0; r < 4; r++) oacc[mt][nt][r] = 0.f;

#pragma unroll 1
    for (int cig = 0; cig < 6; cig++) {
        const float* base = (cig < 2)
            ? Zin + ((size_t)n * 32 + cig * 16) * S
            : hin + ((size_t)n * 64 + (cig * 16 - 32)) * S;
        __syncthreads();
#pragma unroll
        for (int ci = 0; ci < 16; ci++)
            patchF[ci * CPS + pos0] = va0 ? f2tf32(base[(size_t)ci * S + g0]) : 0u;
        if (has1) {
#pragma unroll
            for (int ci = 0; ci < 16; ci++)
                patchF[ci * CPS + pos1] = va1 ? f2tf32(base[(size_t)ci * S + g1]) : 0u;
        }
        for (int i = tid; i < 1152; i += 256) {
            int ln = i & 31, mtc = i >> 5;
            int mt = mtc & 1, chunk = mtc >> 1;
            int khkw = chunk >> 1, c8 = chunk & 1;
            int ciL = c8 * 8 + (ln & 3);
            int co0 = mt * 16 + (ln >> 2);
            const float* wp = Wo + (((size_t)cog * 32 + co0) * 96 + cig * 16 + ciL) * 9 + khkw;
            Wfrag[i] = make_uint4(f2tf32(wp[0]), f2tf32(wp[8 * 864]),
                                  f2tf32(wp[36]), f2tf32(wp[8 * 864 + 36]));
        }
        __syncthreads();

#pragma unroll
        for (int khkw = 0; khkw < 9; khkw++) {
            int kh = khkw / 3, kw = khkw % 3;
#pragma unroll
            for (int c8 = 0; c8 < 2; c8++) {
                int chunk = khkw * 2 + c8;
                uint4 a0 = Wfrag[(chunk * 2 + 0) * 32 + lane];
                uint4 a1 = Wfrag[(chunk * 2 + 1) * 32 + lane];
                const uint32_t* rr = c8 ? rowB : rowA;
#pragma unroll
                for (int nt = 0; nt < 4; nt++) {
                    int off = bbase[nt] + kh * 18 + kw;
                    uint32_t b0 = rr[off];
                    uint32_t b1 = rr[4 * CPS + off];
                    mma1688t(oacc[0][nt], (const uint32_t*)&a0, b0, b1);
                    mma1688t(oacc[1][nt], (const uint32_t*)&a1, b0, b1);
                }
            }
        }
    }

#pragma unroll
    for (int mt = 0; mt < 2; mt++) {
        int coA = cog * 32 + mt * 16 + lq;
        int coB = coA + 8;
        float bA = bo[coA], bB = bo[coB];
        size_t baseA = ((size_t)n * 192 + coA) * S;
        size_t baseB = ((size_t)n * 192 + coB) * S;
#pragma unroll
        for (int nt = 0; nt < 4; nt++) {
            int y = ty0 + 2 * w + (nt >> 1);
            int x = tx0 + (nt & 1) * 8 + 2 * l4;
            *(float2*)&out[baseA + y * WW + x] = make_float2(oacc[mt][nt][0] + bA, oacc[mt][nt][1] + bA);
            *(float2*)&out[baseB + y * WW + x] = make_float2(oacc[mt][nt][2] + bB, oacc[mt][nt][3] + bB);
        }
    }
}

// ---------------- gates (float4) ----------------
__global__ __launch_bounds__(256)
void gates_kernel(const float* __restrict__ conv, const float* __restrict__ m,
                  float* __restrict__ out) {
    int idx4 = blockIdx.x * 256 + threadIdx.x;
    int n = idx4 >> 16;
    int rem = (idx4 & 65535) * 4;
    size_t base = (size_t)n * 192 * S;
    float4 iv = *(const float4*)&conv[base + rem];
    float4 gv = *(const float4*)&conv[base + 64 * S + rem];
    float4 ov = *(const float4*)&conv[base + 128 * S + rem];
    float4 mi = *(const float4*)&m[(size_t)n * 64 * S + rem];
    float4 hn, mn;
    {
        float si = 1.0f / (1.0f + __expf(-iv.x)), gg = tanhf(gv.x), so = 1.0f / (1.0f + __expf(-ov.x));
        mn.x = si * gg + (1.0f - si) * mi.x; hn.x = so * mn.x;
        si = 1.0f / (1.0f + __expf(-iv.y)); gg = tanhf(gv.y); so = 1.0f / (1.0f + __expf(-ov.y));
        mn.y = si * gg + (1.0f - si) * mi.y; hn.y = so * mn.y;
        si = 1.0f / (1.0f + __expf(-iv.z)); gg = tanhf(gv.z); so = 1.0f / (1.0f + __expf(-ov.z));
        mn.z = si * gg + (1.0f - si) * mi.z; hn.z = so * mn.z;
        si = 1.0f / (1.0f + __expf(-iv.w)); gg = tanhf(gv.w); so = 1.0f / (1.0f + __expf(-ov.w));
        mn.w = si * gg + (1.0f - si) * mi.w; hn.w = so * mn.w;
    }
    size_t oidx = (size_t)n * 64 * S + rem;
    *(float4*)&out[oidx] = hn;
    *(float4*)&out[1048576 + oidx] = mn;
}

// ---------------- launch ----------------
extern "C" void kernel_launch(void* const* d_in, const int* in_sizes, int n_in,
                              void* d_out, int out_size) {
    const float* h  = (const float*)d_in[0];
    const float* m  = (const float*)d_in[1];
    const float* Wh = (const float*)d_in[2];
    const float* bh = (const float*)d_in[3];
    const float* Wm = (const float*)d_in[4];
    const float* bm = (const float*)d_in[5];
    const float* Wz = (const float*)d_in[6];
    const float* bz = (const float*)d_in[7];
    const float* Wo = (const float*)d_in[8];
    const float* bo = (const float*)d_in[9];
    float* out = (float*)d_out;

    float *pHqkv, *pMkv, *pZ2, *pZp, *pConv;
    cudaGetSymbolAddress((void**)&pHqkv, g_hqkv);
    cudaGetSymbolAddress((void**)&pMkv,  g_mkv);
    cudaGetSymbolAddress((void**)&pZ2,   g_Z2);
    cudaGetSymbolAddress((void**)&pZp,   g_Zp);
    cudaGetSymbolAddress((void**)&pConv, g_conv);

    projhm_kernel<<<dim3(32, 5, 4), 128>>>(h, Wh, bh, pHqkv, m, Wm, bm, pMkv);
    repack_kernel<<<dim3(64, 2, 4), 256>>>();
    attn_mma_kernel<<<dim3(32, 2, 4), 128>>>(pHqkv, pZ2);
    projz_kernel<<<dim3(64, 1, 4), 128>>>(pZ2, Wz, bz, pZp);
    conv_tc_kernel<<<dim3(16, 6, 4), 256>>>(pZp, h, Wo, bo, pConv);
    gates_kernel<<<1024, 256>>>(pConv, m, out);
}

// round 16
// speedup vs baseline: 1.1699x; 1.0593x over previous
#include <cuda_runtime.h>
#include <cuda_bf16.h>
#include <cuda_fp16.h>
#include <cstdint>

#define S 4096
#define HH 64
#define WW 64

// ---------------- scratch (no allocations allowed) ----------------
__device__ float g_hqkv[4 * 96 * S];
__device__ float g_mkv [4 * 64 * S];
__device__ float g_Z2  [4 * 64 * S];
__device__ float g_Zp  [4 * 32 * S];
__device__ float g_conv[4 * 192 * S];
__device__ uint32_t g_kp[4 * 2 * 65536];   // [n][att][key][dp16] bf16x2
__device__ uint32_t g_vp[4 * 2 * 65536];   // [n][att][d32][kp2048] f16x2

// ---------------- helpers ----------------
__device__ __forceinline__ uint32_t smem_u32(const void* p) {
    uint32_t a;
    asm("{ .reg .u64 t; cvta.to.shared.u64 t, %1; cvt.u32.u64 %0, t; }" : "=r"(a) : "l"(p));
    return a;
}
__device__ __forceinline__ void cpa16(uint32_t dst, const void* src) {
    asm volatile("cp.async.cg.shared.global [%0], [%1], 16;" :: "r"(dst), "l"(src));
}
#define CP_COMMIT() asm volatile("cp.async.commit_group;" ::: "memory")
#define CP_WAIT0()  asm volatile("cp.async.wait_group 0;" ::: "memory")
#define CP_WAIT1()  asm volatile("cp.async.wait_group 1;" ::: "memory")

__device__ __forceinline__ void mma16816(float* c, const uint32_t* a, uint32_t b0, uint32_t b1) {
    asm volatile(
        "mma.sync.aligned.m16n8k16.row.col.f32.bf16.bf16.f32 "
        "{%0,%1,%2,%3}, {%4,%5,%6,%7}, {%8,%9}, {%0,%1,%2,%3};"
        : "+f"(c[0]), "+f"(c[1]), "+f"(c[2]), "+f"(c[3])
        : "r"(a[0]), "r"(a[1]), "r"(a[2]), "r"(a[3]), "r"(b0), "r"(b1));
}
__device__ __forceinline__ void mma16816h(float* c, const uint32_t* a, uint32_t b0, uint32_t b1) {
    asm volatile(
        "mma.sync.aligned.m16n8k16.row.col.f32.f16.f16.f32 "
        "{%0,%1,%2,%3}, {%4,%5,%6,%7}, {%8,%9}, {%0,%1,%2,%3};"
        : "+f"(c[0]), "+f"(c[1]), "+f"(c[2]), "+f"(c[3])
        : "r"(a[0]), "r"(a[1]), "r"(a[2]), "r"(a[3]), "r"(b0), "r"(b1));
}
__device__ __forceinline__ void mma1688t(float* c, const uint32_t* a, uint32_t b0, uint32_t b1) {
    asm volatile(
        "mma.sync.aligned.m16n8k8.row.col.f32.tf32.tf32.f32 "
        "{%0,%1,%2,%3}, {%4,%5,%6,%7}, {%8,%9}, {%0,%1,%2,%3};"
        : "+f"(c[0]), "+f"(c[1]), "+f"(c[2]), "+f"(c[3])
        : "r"(a[0]), "r"(a[1]), "r"(a[2]), "r"(a[3]), "r"(b0), "r"(b1));
}
__device__ __forceinline__ uint32_t packbf(float lo, float hi) {
    uint32_t r;
    asm("cvt.rn.bf16x2.f32 %0, %2, %1;" : "=r"(r) : "f"(lo), "f"(hi));
    return r;
}
__device__ __forceinline__ uint32_t packh(float lo, float hi) {
    uint32_t r;
    asm("cvt.rn.f16x2.f32 %0, %2, %1;" : "=r"(r) : "f"(lo), "f"(hi));
    return r;
}
__device__ __forceinline__ uint32_t h2ex2(uint32_t x) {
    uint32_t r;
    asm("ex2.approx.f16x2 %0, %1;" : "=r"(r) : "r"(x));
    return r;
}
__device__ __forceinline__ uint32_t hadd2u(uint32_t a, uint32_t b) {
    uint32_t r;
    asm("add.rn.f16x2 %0, %1, %2;" : "=r"(r) : "r"(a), "r"(b));
    return r;
}
__device__ __forceinline__ uint32_t f2tf32(float f) {
    uint32_t r;
    asm("cvt.rna.tf32.f32 %0, %1;" : "=r"(r) : "f"(f));
    return r;
}

// ---------------- K/V repack (proven) ----------------
__global__ __launch_bounds__(256)
void repack_kernel() {
    int n = blockIdx.z, att = blockIdx.y, bx = blockIdx.x;
    int t = threadIdx.x;
    const float* K = (att == 0) ? g_hqkv + (size_t)n * 96 * S + 32 * S
                                : g_mkv  + (size_t)n * 64 * S;
    const float* V = (att == 0) ? g_hqkv + (size_t)n * 96 * S + 64 * S
                                : g_mkv  + (size_t)n * 64 * S + 32 * S;
    uint32_t* Kp = g_kp + ((size_t)n * 2 + att) * 65536;
    uint32_t* Vp = g_vp + ((size_t)n * 2 + att) * 65536;
#pragma unroll
    for (int r = 0; r < 4; r++) {
        int j = bx * 1024 + r * 256 + t;
        int key = j & 4095, dp = j >> 12;
        Kp[key * 16 + dp] = packbf(K[(size_t)(2 * dp) * S + key],
                                   K[(size_t)(2 * dp + 1) * S + key]);
        int d = j >> 11, kp = j & 2047;
        float2 v2 = *(const float2*)&V[(size_t)d * S + 2 * kp];
        Vp[d * 2048 + kp] = packh(v2.x, v2.y);
    }
}

// ---------------- 1x1 projection as tf32 GEMM (proven body) ----------------
#define PRJ_XS_ST 136
#define PRJ_WS_ST 40

__device__ __forceinline__ void proj_gemm_body(
    uint32_t* Xs, uint32_t* Ws2,
    const float* Xg, const float* Wg, const float* bg,
    float* outg, int s0)
{
    int tid = threadIdx.x;
    int w = tid >> 5, lane = tid & 31;
    int lq = lane >> 2, l4 = lane & 3;

    for (int i = tid; i < 64 * 128; i += 128) {
        int ci = i >> 7, sl = i & 127;
        Xs[ci * PRJ_XS_ST + sl] = f2tf32(Xg[(size_t)ci * S + s0 + sl]);
    }
    for (int i = tid; i < 32 * 64; i += 128) {
        int co = i >> 6, ci = i & 63;
        Ws2[ci * PRJ_WS_ST + co] = f2tf32(Wg[co * 64 + ci]);
    }
    __syncthreads();

    float oacc[2][4][4];
#pragma unroll
    for (int mt = 0; mt < 2; mt++)
#pragma unroll
        for (int nt = 0; nt < 4; nt++)
#pragma unroll
            for (int r = 0; r < 4; r++) oacc[mt][nt][r] = 0.f;

#pragma unroll
    for (int kb8 = 0; kb8 < 8; kb8++) {
        int kb = kb8 * 8;
        uint32_t a[2][4];
#pragma unroll
        for (int mt = 0; mt < 2; mt++) {
            int co0 = mt * 16 + lq;
            a[mt][0] = Ws2[(kb + l4) * PRJ_WS_ST + co0];
            a[mt][1] = Ws2[(kb + l4) * PRJ_WS_ST + co0 + 8];
            a[mt][2] = Ws2[(kb + l4 + 4) * PRJ_WS_ST + co0];
            a[mt][3] = Ws2[(kb + l4 + 4) * PRJ_WS_ST + co0 + 8];
        }
#pragma unroll
        for (int nt = 0; nt < 4; nt++) {
            int scol = w * 32 + nt * 8 + lq;
            uint32_t b0 = Xs[(kb + l4) * PRJ_XS_ST + scol];
            uint32_t b1 = Xs[(kb + l4 + 4) * PRJ_XS_ST + scol];
            mma1688t(oacc[0][nt], a[0], b0, b1);
            mma1688t(oacc[1][nt], a[1], b0, b1);
        }
    }

#pragma unroll
    for (int mt = 0; mt < 2; mt++) {
        int coA = mt * 16 + lq, coB = coA + 8;
        float bA = bg[coA], bB = bg[coB];
#pragma unroll
        for (int nt = 0; nt < 4; nt++) {
            int x = s0 + w * 32 + nt * 8 + 2 * l4;
            *(float2*)&outg[(size_t)coA * S + x] = make_float2(oacc[mt][nt][0] + bA, oacc[mt][nt][1] + bA);
            *(float2*)&outg[(size_t)coB * S + x] = make_float2(oacc[mt][nt][2] + bB, oacc[mt][nt][3] + bB);
        }
    }
}

__global__ __launch_bounds__(128)
void projhm_kernel(const float* __restrict__ h, const float* __restrict__ Wh,
                   const float* __restrict__ bh, float* __restrict__ hqkv,
                   const float* __restrict__ m, const float* __restrict__ Wm,
                   const float* __restrict__ bm, float* __restrict__ mkv) {
    __shared__ uint32_t Xs[64 * PRJ_XS_ST];
    __shared__ uint32_t Ws2[64 * PRJ_WS_ST];
    int n = blockIdx.z, y = blockIdx.y;
    int s0 = blockIdx.x * 128;
    if (y < 3) {
        int co0 = y * 32;
        proj_gemm_body(Xs, Ws2, h + (size_t)n * 64 * S, Wh + (size_t)co0 * 64, bh + co0,
                       hqkv + ((size_t)n * 96 + co0) * S, s0);
    } else {
        int co0 = (y - 3) * 32;
        proj_gemm_body(Xs, Ws2, m + (size_t)n * 64 * S, Wm + (size_t)co0 * 64, bm + co0,
                       mkv + ((size_t)n * 64 + co0) * S, s0);
    }
}

// ---------------- projz: 32-wide s-tiles, 512 CTAs ----------------
#define PZ_XS_ST 40
__global__ __launch_bounds__(128)
void projz_kernel(const float* __restrict__ Z2, const float* __restrict__ Wz,
                  const float* __restrict__ bz, float* __restrict__ Zp) {
    __shared__ uint32_t Xs[64 * PZ_XS_ST];
    __shared__ uint32_t Ws2[64 * PRJ_WS_ST];
    int tid = threadIdx.x;
    int w = tid >> 5, lane = tid & 31;
    int lq = lane >> 2, l4 = lane & 3;
    int n = blockIdx.z;
    int s0 = blockIdx.x * 32;
    const float* Xg = Z2 + (size_t)n * 64 * S;
    float* outg = Zp + (size_t)n * 32 * S;

    for (int i = tid; i < 64 * 32; i += 128) {
        int ci = i >> 5, sl = i & 31;
        Xs[ci * PZ_XS_ST + sl] = f2tf32(Xg[(size_t)ci * S + s0 + sl]);
    }
    for (int i = tid; i < 32 * 64; i += 128) {
        int co = i >> 6, ci = i & 63;
        Ws2[ci * PRJ_WS_ST + co] = f2tf32(Wz[co * 64 + ci]);
    }
    __syncthreads();

    float oacc[2][4];
#pragma unroll
    for (int mt = 0; mt < 2; mt++)
#pragma unroll
        for (int r = 0; r < 4; r++) oacc[mt][r] = 0.f;

#pragma unroll
    for (int kb8 = 0; kb8 < 8; kb8++) {
        int kb = kb8 * 8;
        uint32_t a[2][4];
#pragma unroll
        for (int mt = 0; mt < 2; mt++) {
            int co0 = mt * 16 + lq;
            a[mt][0] = Ws2[(kb + l4) * PRJ_WS_ST + co0];
            a[mt][1] = Ws2[(kb + l4) * PRJ_WS_ST + co0 + 8];
            a[mt][2] = Ws2[(kb + l4 + 4) * PRJ_WS_ST + co0];
            a[mt][3] = Ws2[(kb + l4 + 4) * PRJ_WS_ST + co0 + 8];
        }
        int scol = w * 8 + lq;
        uint32_t b0 = Xs[(kb + l4) * PZ_XS_ST + scol];
        uint32_t b1 = Xs[(kb + l4 + 4) * PZ_XS_ST + scol];
        mma1688t(oacc[0], a[0], b0, b1);
        mma1688t(oacc[1], a[1], b0, b1);
    }

#pragma unroll
    for (int mt = 0; mt < 2; mt++) {
        int coA = mt * 16 + lq, coB = coA + 8;
        float bA = bz[coA], bB = bz[coB];
        int x = s0 + w * 8 + 2 * l4;
        *(float2*)&outg[(size_t)coA * S + x] = make_float2(oacc[mt][0] + bA, oacc[mt][1] + bA);
        *(float2*)&outg[(size_t)coB * S + x] = make_float2(oacc[mt][2] + bB, oacc[mt][3] + bB);
    }
}

// ---------------- flash attention (round-13/15 proven: 2-buffer cp.async) ----------------
#define AQ_W   2560
#define AK_W   1280
#define AV_W   1152
#define A_TOT  (AQ_W + 2 * AK_W + 2 * AV_W)

__global__ __launch_bounds__(128)
void attn_mma_kernel(const float* __restrict__ hqkv, float* __restrict__ Z2) {
    __shared__ uint32_t smw[A_TOT];
    uint32_t* Qsw = smw;
    uint32_t* Kb0 = smw + AQ_W;
    uint32_t* Vb0 = smw + AQ_W + 2 * AK_W;
    __nv_bfloat16* Qh = (__nv_bfloat16*)Qsw;

    int tid = threadIdx.x;
    int w = tid >> 5, lane = tid & 31;
    int lq = lane >> 2, lj = lane & 3;
    int n = blockIdx.z, att = blockIdx.y;
    int q0 = blockIdx.x * 128;

    const float* Q = hqkv + (size_t)n * 96 * S;
    const uint32_t* Kp = g_kp + ((size_t)n * 2 + att) * 65536;
    const uint32_t* Vp = g_vp + ((size_t)n * 2 + att) * 65536;
    float* Out = Z2 + ((size_t)n * 64 + att * 32) * S;

    uint32_t kb_a[2] = {smem_u32(Kb0), smem_u32(Kb0 + AK_W)};
    uint32_t vb_a[2] = {smem_u32(Vb0), smem_u32(Vb0 + AV_W)};

    int skey = tid >> 1, sqh = tid & 1;
    int svd = tid >> 2, svq = tid & 3;
    uint32_t kdst_off = (skey * 20 + sqh * 8) * 4;
    uint32_t vdst_off = (svd * 36 + svq * 8) * 4;

    const float scale = 0.17677669529663687f * 1.4426950408889634f;
    for (int i = tid; i < 4096; i += 128) {
        int d = i >> 7, q = i & 127;
        Qh[q * 40 + d] = __float2bfloat16(Q[(size_t)d * S + q0 + q] * scale);
    }
    __syncthreads();

    uint32_t qa[2][2][4];
#pragma unroll
    for (int mt = 0; mt < 2; mt++) {
        int r0 = 32 * w + 16 * mt + lq;
#pragma unroll
        for (int ks = 0; ks < 2; ks++) {
            qa[mt][ks][0] = Qsw[r0 * 20 + ks * 8 + lj];
            qa[mt][ks][1] = Qsw[(r0 + 8) * 20 + ks * 8 + lj];
            qa[mt][ks][2] = Qsw[r0 * 20 + ks * 8 + lj + 4];
            qa[mt][ks][3] = Qsw[(r0 + 8) * 20 + ks * 8 + lj + 4];
        }
    }

    float oacc[2][4][4];
#pragma unroll
    for (int mt = 0; mt < 2; mt++)
#pragma unroll
        for (int nt = 0; nt < 4; nt++)
#pragma unroll
            for (int r = 0; r < 4; r++) oacc[mt][nt][r] = 0.f;
    float l_acc[4] = {0.f, 0.f, 0.f, 0.f};

    auto stageA = [&](int kt, int bsel) {
        const uint32_t* ksrc = Kp + ((size_t)(kt * 64 + skey)) * 16 + sqh * 8;
        uint32_t kdst = kb_a[bsel] + kdst_off;
        cpa16(kdst, ksrc);
        cpa16(kdst + 16, ksrc + 4);
        const uint32_t* vsrc = Vp + (size_t)svd * 2048 + kt * 32 + svq * 8;
        uint32_t vdst = vb_a[bsel] + vdst_off;
        cpa16(vdst, vsrc);
        cpa16(vdst + 16, vsrc + 4);
        CP_COMMIT();
    };

    stageA(0, 0);

#pragma unroll 1
    for (int kt = 0; kt < 64; kt++) {
        if (kt < 63) {
            stageA(kt + 1, (kt + 1) & 1);
            CP_WAIT1();
        } else {
            CP_WAIT0();
        }
        __syncthreads();

        const uint32_t* Kbuf = Kb0 + (kt & 1) * AK_W;
        const uint32_t* Vbuf = Vb0 + (kt & 1) * AV_W;

        uint32_t p[2][4][4];
        uint32_t rsh[2][2] = {{0u, 0u}, {0u, 0u}};
#pragma unroll
        for (int nn = 0; nn < 8; nn++) {
            float c[2][4];
#pragma unroll
            for (int mt = 0; mt < 2; mt++)
#pragma unroll
                for (int r = 0; r < 4; r++) c[mt][r] = 0.f;
#pragma unroll
            for (int ks = 0; ks < 2; ks++) {
                int bw = (nn * 8 + lq) * 20 + ks * 8 + lj;
                uint32_t b0 = Kbuf[bw], b1 = Kbuf[bw + 4];
                mma16816(c[0], qa[0][ks], b0, b1);
                mma16816(c[1], qa[1][ks], b0, b1);
            }
            int kk = nn >> 1, half = (nn & 1) * 2;
#pragma unroll
            for (int mt = 0; mt < 2; mt++) {
                uint32_t p01 = h2ex2(packh(c[mt][0], c[mt][1]));
                uint32_t p23 = h2ex2(packh(c[mt][2], c[mt][3]));
                rsh[mt][0] = hadd2u(rsh[mt][0], p01);
                rsh[mt][1] = hadd2u(rsh[mt][1], p23);
                p[mt][kk][half + 0] = p01;
                p[mt][kk][half + 1] = p23;
            }
        }
#pragma unroll
        for (int mt = 0; mt < 2; mt++) {
            float2 f0 = __half22float2(*(__half2*)&rsh[mt][0]);
            float2 f1 = __half22float2(*(__half2*)&rsh[mt][1]);
            float r0 = f0.x + f0.y, r1 = f1.x + f1.y;
            r0 += __shfl_xor_sync(0xffffffffu, r0, 1);
            r0 += __shfl_xor_sync(0xffffffffu, r0, 2);
            r1 += __shfl_xor_sync(0xffffffffu, r1, 1);
            r1 += __shfl_xor_sync(0xffffffffu, r1, 2);
            l_acc[mt * 2 + 0] += r0;
            l_acc[mt * 2 + 1] += r1;
        }

#pragma unroll
        for (int nt = 0; nt < 4; nt++) {
#pragma unroll
            for (int kk = 0; kk < 4; kk++) {
                int bw = (nt * 8 + lq) * 36 + kk * 8 + lj;
                uint32_t b0 = Vbuf[bw], b1 = Vbuf[bw + 4];
                mma16816h(oacc[0][nt], p[0][kk], b0, b1);
                mma16816h(oacc[1][nt], p[1][kk], b0, b1);
            }
        }
        __syncthreads();
    }

    // ---- epilogue
    float* Osm = (float*)smw;
    float inv[4];
#pragma unroll
    for (int r = 0; r < 4; r++) inv[r] = 1.0f / l_acc[r];
#pragma unroll
    for (int mt = 0; mt < 2; mt++) {
        int r0 = 32 * w + 16 * mt + lq;
#pragma unroll
        for (int nt = 0; nt < 4; nt++) {
            int d0 = nt * 8 + 2 * lj;
            Osm[(d0 + 0) * 130 + r0]     = oacc[mt][nt][0] * inv[mt * 2];
            Osm[(d0 + 1) * 130 + r0]     = oacc[mt][nt][1] * inv[mt * 2];
            Osm[(d0 + 0) * 130 + r0 + 8] = oacc[mt][nt][2] * inv[mt * 2 + 1];
            Osm[(d0 + 1) * 130 + r0 + 8] = oacc[mt][nt][3] * inv[mt * 2 + 1];
        }
    }
    __syncthreads();
    for (int i = tid; i < 4096; i += 128) {
        int d = i >> 7, q = i & 127;
        Out[(size_t)d * S + q0 + q] = Osm[d * 130 + q];
    }
}

// ---------------- 3x3 conv implicit GEMM on f16 mma.sync ----------------
// patchH[cp][pixel] f16x2 of ci-pair (2cp, 2cp+1); 8 rows x stride 328.
// Wfrag[khkw*2+mt][lane] = uint4 A-fragment (k-pairs packed f16x2).
// Per khkw: 1 k16 MMA step x (2 mt x 4 nt) = 8 MMAs, 8 LDS.
#define CPS 328
__global__ __launch_bounds__(256)
void conv_tc_kernel(const float* __restrict__ Zin, const float* __restrict__ hin,
                    const float* __restrict__ Wo, const float* __restrict__ bo,
                    float* __restrict__ out) {
    __shared__ uint32_t patchH[8 * CPS];
    __shared__ uint4 Wfrag[18 * 32];

    int tid = threadIdx.x;
    int w = tid >> 5, lane = tid & 31;
    int lq = lane >> 2, l4 = lane & 3;
    int n = blockIdx.z, cog = blockIdx.y, tile = blockIdx.x;
    int ty0 = (tile >> 2) * 16, tx0 = (tile & 3) * 16;

    int pos0 = tid;
    int yy0 = pos0 / 18 + ty0 - 1, xx0 = pos0 % 18 + tx0 - 1;
    bool va0 = (yy0 >= 0 && yy0 < HH && xx0 >= 0 && xx0 < WW);
    int g0 = yy0 * WW + xx0;
    int pos1 = tid + 256;
    bool has1 = pos1 < 324;
    int yy1 = pos1 / 18 + ty0 - 1, xx1 = pos1 % 18 + tx0 - 1;
    bool va1 = has1 && (yy1 >= 0 && yy1 < HH && xx1 >= 0 && xx1 < WW);
    int g1 = yy1 * WW + xx1;

    const uint32_t* rowA = patchH + l4 * CPS;        // cp = lj
    const uint32_t* rowB = patchH + (4 + l4) * CPS;  // cp = lj + 4
    int bbase[4];
#pragma unroll
    for (int nt = 0; nt < 4; nt++)
        bbase[nt] = (2 * w + (nt >> 1)) * 18 + (nt & 1) * 8 + lq;

    float oacc[2][4][4];
#pragma unroll
    for (int mt = 0; mt < 2; mt++)
#pragma unroll
        for (int nt = 0; nt < 4; nt++)
#pragma unroll
            for (int r = 0; r < 4; r++) oacc[mt][nt][r] = 0.f;

#pragma unroll 1
    for (int cig = 0; cig < 6; cig++) {
        const float* base = (cig < 2)
            ? Zin + ((size_t)n * 32 + cig * 16) * S
            : hin + ((size_t)n * 64 + (cig * 16 - 32)) * S;
        __syncthreads();
        // stage patch: thread covers its 2 fixed positions across 8 ci-pairs
#pragma unroll
        for (int cp = 0; cp < 8; cp++) {
            float v0 = va0 ? base[(size_t)(2 * cp) * S + g0] : 0.f;
            float v1 = va0 ? base[(size_t)(2 * cp + 1) * S + g0] : 0.f;
            patchH[cp * CPS + pos0] = packh(v0, v1);
        }
        if (has1) {
#pragma unroll
            for (int cp = 0; cp < 8; cp++) {
                float v0 = va1 ? base[(size_t)(2 * cp) * S + g1] : 0.f;
                float v1 = va1 ? base[(size_t)(2 * cp + 1) * S + g1] : 0.f;
                patchH[cp * CPS + pos1] = packh(v0, v1);
            }
        }
        // stage weights as f16 A-fragments: Wfrag[(khkw*2+mt)*32 + lane]
        for (int i = tid; i < 576; i += 256) {
            int ln = i & 31, rest = i >> 5;
            int mt = rest & 1, khkw = rest >> 1;
            int llq = ln >> 2, llj = ln & 3;
            int co0 = cog * 32 + mt * 16 + llq;
            const float* wb = Wo + ((size_t)co0 * 96 + cig * 16) * 9 + khkw;
            uint4 f;
            f.x = packh(wb[(2 * llj) * 9],     wb[(2 * llj + 1) * 9]);
            f.y = packh(wb[864 * 8 + (2 * llj) * 9], wb[864 * 8 + (2 * llj + 1) * 9]);
            f.z = packh(wb[(2 * llj + 8) * 9], wb[(2 * llj + 9) * 9]);
            f.w = packh(wb[864 * 8 + (2 * llj + 8) * 9], wb[864 * 8 + (2 * llj + 9) * 9]);
            Wfrag[i] = f;
        }
        __syncthreads();

#pragma unroll
        for (int khkw = 0; khkw < 9; khkw++) {
            int kh = khkw / 3, kw = khkw % 3;
            uint4 a0 = Wfrag[(khkw * 2 + 0) * 32 + lane];
            uint4 a1 = Wfrag[(khkw * 2 + 1) * 32 + lane];
#pragma unroll
            for (int nt = 0; nt < 4; nt++) {
                int off = bbase[nt] + kh * 18 + kw;
                uint32_t b0 = rowA[off];
                uint32_t b1 = rowB[off];
                mma16816h(oacc[0][nt], (const uint32_t*)&a0, b0, b1);
                mma16816h(oacc[1][nt], (const uint32_t*)&a1, b0, b1);
            }
        }
    }

#pragma unroll
    for (int mt = 0; mt < 2; mt++) {
        int coA = cog * 32 + mt * 16 + lq;
        int coB = coA + 8;
        float bA = bo[coA], bB = bo[coB];
        size_t baseA = ((size_t)n * 192 + coA) * S;
        size_t baseB = ((size_t)n * 192 + coB) * S;
#pragma unroll
        for (int nt = 0; nt < 4; nt++) {
            int y = ty0 + 2 * w + (nt >> 1);
            int x = tx0 + (nt & 1) * 8 + 2 * l4;
            *(float2*)&out[baseA + y * WW + x] = make_float2(oacc[mt][nt][0] + bA, oacc[mt][nt][1] + bA);
            *(float2*)&out[baseB + y * WW + x] = make_float2(oacc[mt][nt][2] + bB, oacc[mt][nt][3] + bB);
        }
    }
}

// ---------------- gates (float4) ----------------
__global__ __launch_bounds__(256)
void gates_kernel(const float* __restrict__ conv, const float* __restrict__ m,
                  float* __restrict__ out) {
    int idx4 = blockIdx.x * 256 + threadIdx.x;
    int n = idx4 >> 16;
    int rem = (idx4 & 65535) * 4;
    size_t base = (size_t)n * 192 * S;
    float4 iv = *(const float4*)&conv[base + rem];
    float4 gv = *(const float4*)&conv[base + 64 * S + rem];
    float4 ov = *(const float4*)&conv[base + 128 * S + rem];
    float4 mi = *(const float4*)&m[(size_t)n * 64 * S + rem];
    float4 hn, mn;
    {
        float si = 1.0f / (1.0f + __expf(-iv.x)), gg = tanhf(gv.x), so = 1.0f / (1.0f + __expf(-ov.x));
        mn.x = si * gg + (1.0f - si) * mi.x; hn.x = so * mn.x;
        si = 1.0f / (1.0f + __expf(-iv.y)); gg = tanhf(gv.y); so = 1.0f / (1.0f + __expf(-ov.y));
        mn.y = si * gg + (1.0f - si) * mi.y; hn.y = so * mn.y;
        si = 1.0f / (1.0f + __expf(-iv.z)); gg = tanhf(gv.z); so = 1.0f / (1.0f + __expf(-ov.z));
        mn.z = si * gg + (1.0f - si) * mi.z; hn.z = so * mn.z;
        si = 1.0f / (1.0f + __expf(-iv.w)); gg = tanhf(gv.w); so = 1.0f / (1.0f + __expf(-ov.w));
        mn.w = si * gg + (1.0f - si) * mi.w; hn.w = so * mn.w;
    }
    size_t oidx = (size_t)n * 64 * S + rem;
    *(float4*)&out[oidx] = hn;
    *(float4*)&out[1048576 + oidx] = mn;
}

// ---------------- launch ----------------
extern "C" void kernel_launch(void* const* d_in, const int* in_sizes, int n_in,
                              void* d_out, int out_size) {
    const float* h  = (const float*)d_in[0];
    const float* m  = (const float*)d_in[1];
    const float* Wh = (const float*)d_in[2];
    const float* bh = (const float*)d_in[3];
    const float* Wm = (const float*)d_in[4];
    const float* bm = (const float*)d_in[5];
    const float* Wz = (const float*)d_in[6];
    const float* bz = (const float*)d_in[7];
    const float* Wo = (const float*)d_in[8];
    const float* bo = (const float*)d_in[9];
    float* out = (float*)d_out;

    float *pHqkv, *pMkv, *pZ2, *pZp, *pConv;
    cudaGetSymbolAddress((void**)&pHqkv, g_hqkv);
    cudaGetSymbolAddress((void**)&pMkv,  g_mkv);
    cudaGetSymbolAddress((void**)&pZ2,   g_Z2);
    cudaGetSymbolAddress((void**)&pZp,   g_Zp);
    cudaGetSymbolAddress((void**)&pConv, g_conv);

    projhm_kernel<<<dim3(32, 5, 4), 128>>>(h, Wh, bh, pHqkv, m, Wm, bm, pMkv);
    repack_kernel<<<dim3(64, 2, 4), 256>>>();
    attn_mma_kernel<<<dim3(32, 2, 4), 128>>>(pHqkv, pZ2);
    projz_kernel<<<dim3(128, 1, 4), 128>>>(pZ2, Wz, bz, pZp);
    conv_tc_kernel<<<dim3(16, 6, 4), 256>>>(pZp, h, Wo, bo, pConv);
    gates_kernel<<<1024, 256>>>(pConv, m, out);
}

// round 17
// speedup vs baseline: 1.2025x; 1.0278x over previous
#include <cuda_runtime.h>
#include <cuda_bf16.h>
#include <cuda_fp16.h>
#include <cstdint>

#define S 4096
#define HH 64
#define WW 64

// ---------------- scratch (no allocations allowed) ----------------
__device__ float g_hqkv[4 * 96 * S];
__device__ float g_mkv [4 * 64 * S];
__device__ float g_Z2  [4 * 64 * S];
__device__ float g_Zp  [4 * 32 * S];
__device__ float g_conv[4 * 192 * S];
__device__ uint32_t g_kp[4 * 2 * 65536];   // [n][att][key][dp16] bf16x2
__device__ uint32_t g_vp[4 * 2 * 65536];   // [n][att][d32][kp2048] f16x2

// ---------------- helpers ----------------
__device__ __forceinline__ uint32_t smem_u32(const void* p) {
    uint32_t a;
    asm("{ .reg .u64 t; cvta.to.shared.u64 t, %1; cvt.u32.u64 %0, t; }" : "=r"(a) : "l"(p));
    return a;
}
__device__ __forceinline__ void cpa16(uint32_t dst, const void* src) {
    asm volatile("cp.async.cg.shared.global [%0], [%1], 16;" :: "r"(dst), "l"(src));
}
#define CP_COMMIT() asm volatile("cp.async.commit_group;" ::: "memory")
#define CP_WAIT0()  asm volatile("cp.async.wait_group 0;" ::: "memory")
#define CP_WAIT1()  asm volatile("cp.async.wait_group 1;" ::: "memory")

__device__ __forceinline__ void mma16816(float* c, const uint32_t* a, uint32_t b0, uint32_t b1) {
    asm volatile(
        "mma.sync.aligned.m16n8k16.row.col.f32.bf16.bf16.f32 "
        "{%0,%1,%2,%3}, {%4,%5,%6,%7}, {%8,%9}, {%0,%1,%2,%3};"
        : "+f"(c[0]), "+f"(c[1]), "+f"(c[2]), "+f"(c[3])
        : "r"(a[0]), "r"(a[1]), "r"(a[2]), "r"(a[3]), "r"(b0), "r"(b1));
}
__device__ __forceinline__ void mma16816h(float* c, const uint32_t* a, uint32_t b0, uint32_t b1) {
    asm volatile(
        "mma.sync.aligned.m16n8k16.row.col.f32.f16.f16.f32 "
        "{%0,%1,%2,%3}, {%4,%5,%6,%7}, {%8,%9}, {%0,%1,%2,%3};"
        : "+f"(c[0]), "+f"(c[1]), "+f"(c[2]), "+f"(c[3])
        : "r"(a[0]), "r"(a[1]), "r"(a[2]), "r"(a[3]), "r"(b0), "r"(b1));
}
__device__ __forceinline__ void mma1688t(float* c, const uint32_t* a, uint32_t b0, uint32_t b1) {
    asm volatile(
        "mma.sync.aligned.m16n8k8.row.col.f32.tf32.tf32.f32 "
        "{%0,%1,%2,%3}, {%4,%5,%6,%7}, {%8,%9}, {%0,%1,%2,%3};"
        : "+f"(c[0]), "+f"(c[1]), "+f"(c[2]), "+f"(c[3])
        : "r"(a[0]), "r"(a[1]), "r"(a[2]), "r"(a[3]), "r"(b0), "r"(b1));
}
__device__ __forceinline__ uint32_t packbf(float lo, float hi) {
    uint32_t r;
    asm("cvt.rn.bf16x2.f32 %0, %2, %1;" : "=r"(r) : "f"(lo), "f"(hi));
    return r;
}
__device__ __forceinline__ uint32_t packh(float lo, float hi) {
    uint32_t r;
    asm("cvt.rn.f16x2.f32 %0, %2, %1;" : "=r"(r) : "f"(lo), "f"(hi));
    return r;
}
__device__ __forceinline__ uint32_t h2ex2(uint32_t x) {
    uint32_t r;
    asm("ex2.approx.f16x2 %0, %1;" : "=r"(r) : "r"(x));
    return r;
}
__device__ __forceinline__ uint32_t hadd2u(uint32_t a, uint32_t b) {
    uint32_t r;
    asm("add.rn.f16x2 %0, %1, %2;" : "=r"(r) : "r"(a), "r"(b));
    return r;
}
__device__ __forceinline__ uint32_t f2tf32(float f) {
    uint32_t r;
    asm("cvt.rna.tf32.f32 %0, %1;" : "=r"(r) : "f"(f));
    return r;
}

// ---------------- K/V repack (proven) ----------------
__global__ __launch_bounds__(256)
void repack_kernel() {
    int n = blockIdx.z, att = blockIdx.y, bx = blockIdx.x;
    int t = threadIdx.x;
    const float* K = (att == 0) ? g_hqkv + (size_t)n * 96 * S + 32 * S
                                : g_mkv  + (size_t)n * 64 * S;
    const float* V = (att == 0) ? g_hqkv + (size_t)n * 96 * S + 64 * S
                                : g_mkv  + (size_t)n * 64 * S + 32 * S;
    uint32_t* Kp = g_kp + ((size_t)n * 2 + att) * 65536;
    uint32_t* Vp = g_vp + ((size_t)n * 2 + att) * 65536;
#pragma unroll
    for (int r = 0; r < 4; r++) {
        int j = bx * 1024 + r * 256 + t;
        int key = j & 4095, dp = j >> 12;
        Kp[key * 16 + dp] = packbf(K[(size_t)(2 * dp) * S + key],
                                   K[(size_t)(2 * dp + 1) * S + key]);
        int d = j >> 11, kp = j & 2047;
        float2 v2 = *(const float2*)&V[(size_t)d * S + 2 * kp];
        Vp[d * 2048 + kp] = packh(v2.x, v2.y);
    }
}

// ---------------- 1x1 projection as tf32 GEMM (proven body) ----------------
#define PRJ_XS_ST 136
#define PRJ_WS_ST 40

__device__ __forceinline__ void proj_gemm_body(
    uint32_t* Xs, uint32_t* Ws2,
    const float* Xg, const float* Wg, const float* bg,
    float* outg, int s0)
{
    int tid = threadIdx.x;
    int w = tid >> 5, lane = tid & 31;
    int lq = lane >> 2, l4 = lane & 3;

    for (int i = tid; i < 64 * 128; i += 128) {
        int ci = i >> 7, sl = i & 127;
        Xs[ci * PRJ_XS_ST + sl] = f2tf32(Xg[(size_t)ci * S + s0 + sl]);
    }
    for (int i = tid; i < 32 * 64; i += 128) {
        int co = i >> 6, ci = i & 63;
        Ws2[ci * PRJ_WS_ST + co] = f2tf32(Wg[co * 64 + ci]);
    }
    __syncthreads();

    float oacc[2][4][4];
#pragma unroll
    for (int mt = 0; mt < 2; mt++)
#pragma unroll
        for (int nt = 0; nt < 4; nt++)
#pragma unroll
            for (int r = 0; r < 4; r++) oacc[mt][nt][r] = 0.f;

#pragma unroll
    for (int kb8 = 0; kb8 < 8; kb8++) {
        int kb = kb8 * 8;
        uint32_t a[2][4];
#pragma unroll
        for (int mt = 0; mt < 2; mt++) {
            int co0 = mt * 16 + lq;
            a[mt][0] = Ws2[(kb + l4) * PRJ_WS_ST + co0];
            a[mt][1] = Ws2[(kb + l4) * PRJ_WS_ST + co0 + 8];
            a[mt][2] = Ws2[(kb + l4 + 4) * PRJ_WS_ST + co0];
            a[mt][3] = Ws2[(kb + l4 + 4) * PRJ_WS_ST + co0 + 8];
        }
#pragma unroll
        for (int nt = 0; nt < 4; nt++) {
            int scol = w * 32 + nt * 8 + lq;
            uint32_t b0 = Xs[(kb + l4) * PRJ_XS_ST + scol];
            uint32_t b1 = Xs[(kb + l4 + 4) * PRJ_XS_ST + scol];
            mma1688t(oacc[0][nt], a[0], b0, b1);
            mma1688t(oacc[1][nt], a[1], b0, b1);
        }
    }

#pragma unroll
    for (int mt = 0; mt < 2; mt++) {
        int coA = mt * 16 + lq, coB = coA + 8;
        float bA = bg[coA], bB = bg[coB];
#pragma unroll
        for (int nt = 0; nt < 4; nt++) {
            int x = s0 + w * 32 + nt * 8 + 2 * l4;
            *(float2*)&outg[(size_t)coA * S + x] = make_float2(oacc[mt][nt][0] + bA, oacc[mt][nt][1] + bA);
            *(float2*)&outg[(size_t)coB * S + x] = make_float2(oacc[mt][nt][2] + bB, oacc[mt][nt][3] + bB);
        }
    }
}

__global__ __launch_bounds__(128)
void projhm_kernel(const float* __restrict__ h, const float* __restrict__ Wh,
                   const float* __restrict__ bh, float* __restrict__ hqkv,
                   const float* __restrict__ m, const float* __restrict__ Wm,
                   const float* __restrict__ bm, float* __restrict__ mkv) {
    __shared__ uint32_t Xs[64 * PRJ_XS_ST];
    __shared__ uint32_t Ws2[64 * PRJ_WS_ST];
    int n = blockIdx.z, y = blockIdx.y;
    int s0 = blockIdx.x * 128;
    if (y < 3) {
        int co0 = y * 32;
        proj_gemm_body(Xs, Ws2, h + (size_t)n * 64 * S, Wh + (size_t)co0 * 64, bh + co0,
                       hqkv + ((size_t)n * 96 + co0) * S, s0);
    } else {
        int co0 = (y - 3) * 32;
        proj_gemm_body(Xs, Ws2, m + (size_t)n * 64 * S, Wm + (size_t)co0 * 64, bm + co0,
                       mkv + ((size_t)n * 64 + co0) * S, s0);
    }
}

// ---------------- projz: 64-wide s-tiles, 256 CTAs (round-15 proven) ----------------
#define PZ_XS_ST 72
__global__ __launch_bounds__(128)
void projz_kernel(const float* __restrict__ Z2, const float* __restrict__ Wz,
                  const float* __restrict__ bz, float* __restrict__ Zp) {
    __shared__ uint32_t Xs[64 * PZ_XS_ST];
    __shared__ uint32_t Ws2[64 * PRJ_WS_ST];
    int tid = threadIdx.x;
    int w = tid >> 5, lane = tid & 31;
    int lq = lane >> 2, l4 = lane & 3;
    int n = blockIdx.z;
    int s0 = blockIdx.x * 64;
    const float* Xg = Z2 + (size_t)n * 64 * S;
    float* outg = Zp + (size_t)n * 32 * S;

    for (int i = tid; i < 64 * 64; i += 128) {
        int ci = i >> 6, sl = i & 63;
        Xs[ci * PZ_XS_ST + sl] = f2tf32(Xg[(size_t)ci * S + s0 + sl]);
    }
    for (int i = tid; i < 32 * 64; i += 128) {
        int co = i >> 6, ci = i & 63;
        Ws2[ci * PRJ_WS_ST + co] = f2tf32(Wz[co * 64 + ci]);
    }
    __syncthreads();

    float oacc[2][2][4];
#pragma unroll
    for (int mt = 0; mt < 2; mt++)
#pragma unroll
        for (int nt = 0; nt < 2; nt++)
#pragma unroll
            for (int r = 0; r < 4; r++) oacc[mt][nt][r] = 0.f;

#pragma unroll
    for (int kb8 = 0; kb8 < 8; kb8++) {
        int kb = kb8 * 8;
        uint32_t a[2][4];
#pragma unroll
        for (int mt = 0; mt < 2; mt++) {
            int co0 = mt * 16 + lq;
            a[mt][0] = Ws2[(kb + l4) * PRJ_WS_ST + co0];
            a[mt][1] = Ws2[(kb + l4) * PRJ_WS_ST + co0 + 8];
            a[mt][2] = Ws2[(kb + l4 + 4) * PRJ_WS_ST + co0];
            a[mt][3] = Ws2[(kb + l4 + 4) * PRJ_WS_ST + co0 + 8];
        }
#pragma unroll
        for (int nt = 0; nt < 2; nt++) {
            int scol = w * 16 + nt * 8 + lq;
            uint32_t b0 = Xs[(kb + l4) * PZ_XS_ST + scol];
            uint32_t b1 = Xs[(kb + l4 + 4) * PZ_XS_ST + scol];
            mma1688t(oacc[0][nt], a[0], b0, b1);
            mma1688t(oacc[1][nt], a[1], b0, b1);
        }
    }

#pragma unroll
    for (int mt = 0; mt < 2; mt++) {
        int coA = mt * 16 + lq, coB = coA + 8;
        float bA = bz[coA], bB = bz[coB];
#pragma unroll
        for (int nt = 0; nt < 2; nt++) {
            int x = s0 + w * 16 + nt * 8 + 2 * l4;
            *(float2*)&outg[(size_t)coA * S + x] = make_float2(oacc[mt][nt][0] + bA, oacc[mt][nt][1] + bA);
            *(float2*)&outg[(size_t)coB * S + x] = make_float2(oacc[mt][nt][2] + bB, oacc[mt][nt][3] + bB);
        }
    }
}

// ---------------- flash attention: 256 thr / 8 warps, 16 query rows per warp ----------------
// smem words: Qs 128x20 = 2560 | Kbuf[2] 64x20 = 1280 ea | Vbuf[2] 32x36 = 1152 ea
#define AQ_W   2560
#define AK_W   1280
#define AV_W   1152
#define A_TOT  (AQ_W + 2 * AK_W + 2 * AV_W)

__global__ __launch_bounds__(256)
void attn_mma_kernel(const float* __restrict__ hqkv, float* __restrict__ Z2) {
    __shared__ uint32_t smw[A_TOT];
    uint32_t* Qsw = smw;
    uint32_t* Kb0 = smw + AQ_W;
    uint32_t* Vb0 = smw + AQ_W + 2 * AK_W;
    __nv_bfloat16* Qh = (__nv_bfloat16*)Qsw;

    int tid = threadIdx.x;
    int w = tid >> 5, lane = tid & 31;
    int lq = lane >> 2, lj = lane & 3;
    int n = blockIdx.z, att = blockIdx.y;
    int q0 = blockIdx.x * 128;

    const float* Q = hqkv + (size_t)n * 96 * S;
    const uint32_t* Kp = g_kp + ((size_t)n * 2 + att) * 65536;
    const uint32_t* Vp = g_vp + ((size_t)n * 2 + att) * 65536;
    float* Out = Z2 + ((size_t)n * 64 + att * 32) * S;

    uint32_t kb_a[2] = {smem_u32(Kb0), smem_u32(Kb0 + AK_W)};
    uint32_t vb_a[2] = {smem_u32(Vb0), smem_u32(Vb0 + AV_W)};

    // per-thread staging: 1 x 16B K + 1 x 16B V per chunk
    int skey = tid >> 2, sq4 = tid & 3;          // K: key row, quarter
    int svd = tid >> 3, sv8 = tid & 7;           // V: d row, eighth
    uint32_t kdst_off = (skey * 20 + sq4 * 4) * 4;
    uint32_t vdst_off = (svd * 36 + sv8 * 4) * 4;

    const float scale = 0.17677669529663687f * 1.4426950408889634f;  // log2e/sqrt(32)
    for (int i = tid; i < 4096; i += 256) {
        int d = i >> 7, q = i & 127;
        Qh[q * 40 + d] = __float2bfloat16(Q[(size_t)d * S + q0 + q] * scale);
    }
    __syncthreads();

    // warp w owns query rows 16w .. 16w+15 (one m16 tile)
    uint32_t qa[2][4];
    {
        int r0 = 16 * w + lq;
#pragma unroll
        for (int ks = 0; ks < 2; ks++) {
            qa[ks][0] = Qsw[r0 * 20 + ks * 8 + lj];
            qa[ks][1] = Qsw[(r0 + 8) * 20 + ks * 8 + lj];
            qa[ks][2] = Qsw[r0 * 20 + ks * 8 + lj + 4];
            qa[ks][3] = Qsw[(r0 + 8) * 20 + ks * 8 + lj + 4];
        }
    }

    float oacc[4][4];
#pragma unroll
    for (int nt = 0; nt < 4; nt++)
#pragma unroll
        for (int r = 0; r < 4; r++) oacc[nt][r] = 0.f;
    float l_acc[2] = {0.f, 0.f};

    auto stageA = [&](int kt, int bsel) {
        cpa16(kb_a[bsel] + kdst_off, Kp + ((size_t)(kt * 64 + skey)) * 16 + sq4 * 4);
        cpa16(vb_a[bsel] + vdst_off, Vp + (size_t)svd * 2048 + kt * 32 + sv8 * 4);
        CP_COMMIT();
    };

    stageA(0, 0);

#pragma unroll 1
    for (int kt = 0; kt < 64; kt++) {
        if (kt < 63) {
            stageA(kt + 1, (kt + 1) & 1);
            CP_WAIT1();
        } else {
            CP_WAIT0();
        }
        __syncthreads();

        const uint32_t* Kbuf = Kb0 + (kt & 1) * AK_W;
        const uint32_t* Vbuf = Vb0 + (kt & 1) * AV_W;

        uint32_t p[4][4];
        uint32_t rsh[2] = {0u, 0u};
#pragma unroll
        for (int nn = 0; nn < 8; nn++) {
            float c[4] = {0.f, 0.f, 0.f, 0.f};
#pragma unroll
            for (int ks = 0; ks < 2; ks++) {
                int bw = (nn * 8 + lq) * 20 + ks * 8 + lj;
                mma16816(c, qa[ks], Kbuf[bw], Kbuf[bw + 4]);
            }
            int kk = nn >> 1, half = (nn & 1) * 2;
            uint32_t p01 = h2ex2(packh(c[0], c[1]));
            uint32_t p23 = h2ex2(packh(c[2], c[3]));
            rsh[0] = hadd2u(rsh[0], p01);
            rsh[1] = hadd2u(rsh[1], p23);
            p[kk][half + 0] = p01;
            p[kk][half + 1] = p23;
        }
        {
            float2 f0 = __half22float2(*(__half2*)&rsh[0]);
            float2 f1 = __half22float2(*(__half2*)&rsh[1]);
            float r0 = f0.x + f0.y, r1 = f1.x + f1.y;
            r0 += __shfl_xor_sync(0xffffffffu, r0, 1);
            r0 += __shfl_xor_sync(0xffffffffu, r0, 2);
            r1 += __shfl_xor_sync(0xffffffffu, r1, 1);
            r1 += __shfl_xor_sync(0xffffffffu, r1, 2);
            l_acc[0] += r0;
            l_acc[1] += r1;
        }

#pragma unroll
        for (int nt = 0; nt < 4; nt++) {
#pragma unroll
            for (int kk = 0; kk < 4; kk++) {
                int bw = (nt * 8 + lq) * 36 + kk * 8 + lj;
                mma16816h(oacc[nt], p[kk], Vbuf[bw], Vbuf[bw + 4]);
            }
        }
        __syncthreads();
    }

    // ---- epilogue: normalize, stage Osm[d][q] stride 130, coalesced store
    float* Osm = (float*)smw;
    float inv0 = 1.0f / l_acc[0], inv1 = 1.0f / l_acc[1];
    int r0 = 16 * w + lq;
#pragma unroll
    for (int nt = 0; nt < 4; nt++) {
        int d0 = nt * 8 + 2 * lj;
        Osm[(d0 + 0) * 130 + r0]     = oacc[nt][0] * inv0;
        Osm[(d0 + 1) * 130 + r0]     = oacc[nt][1] * inv0;
        Osm[(d0 + 0) * 130 + r0 + 8] = oacc[nt][2] * inv1;
        Osm[(d0 + 1) * 130 + r0 + 8] = oacc[nt][3] * inv1;
    }
    __syncthreads();
    for (int i = tid; i < 4096; i += 256) {
        int d = i >> 7, q = i & 127;
        Out[(size_t)d * S + q0 + q] = Osm[d * 130 + q];
    }
}

// ---------------- 3x3 conv implicit GEMM on f16 mma.sync (round-16 proven) ----------------
#define CPS 328
__global__ __launch_bounds__(256)
void conv_tc_kernel(const float* __restrict__ Zin, const float* __restrict__ hin,
                    const float* __restrict__ Wo, const float* __restrict__ bo,
                    float* __restrict__ out) {
    __shared__ uint32_t patchH[8 * CPS];
    __shared__ uint4 Wfrag[18 * 32];

    int tid = threadIdx.x;
    int w = tid >> 5, lane = tid & 31;
    int lq = lane >> 2, l4 = lane & 3;
    int n = blockIdx.z, cog = blockIdx.y, tile = blockIdx.x;
    int ty0 = (tile >> 2) * 16, tx0 = (tile & 3) * 16;

    int pos0 = tid;
    int yy0 = pos0 / 18 + ty0 - 1, xx0 = pos0 % 18 + tx0 - 1;
    bool va0 = (yy0 >= 0 && yy0 < HH && xx0 >= 0 && xx0 < WW);
    int g0 = yy0 * WW + xx0;
    int pos1 = tid + 256;
    bool has1 = pos1 < 324;
    int yy1 = pos1 / 18 + ty0 - 1, xx1 = pos1 % 18 + tx0 - 1;
    bool va1 = has1 && (yy1 >= 0 && yy1 < HH && xx1 >= 0 && xx1 < WW);
    int g1 = yy1 * WW + xx1;

    const uint32_t* rowA = patchH + l4 * CPS;
    const uint32_t* rowB = patchH + (4 + l4) * CPS;
    int bbase[4];
#pragma unroll
    for (int nt = 0; nt < 4; nt++)
        bbase[nt] = (2 * w + (nt >> 1)) * 18 + (nt & 1) * 8 + lq;

    float oacc[2][4][4];
#pragma unroll
    for (int mt = 0; mt < 2; mt++)
#pragma unroll
        for (int nt = 0; nt < 4; nt++)
#pragma unroll
            for (int r = 0; r < 4; r++) oacc[mt][nt][r] = 0.f;

#pragma unroll 1
    for (int cig = 0; cig < 6; cig++) {
        const float* base = (cig < 2)
            ? Zin + ((size_t)n * 32 + cig * 16) * S
            : hin + ((size_t)n * 64 + (cig * 16 - 32)) * S;
        __syncthreads();
#pragma unroll
        for (int cp = 0; cp < 8; cp++) {
            float v0 = va0 ? base[(size_t)(2 * cp) * S + g0] : 0.f;
            float v1 = va0 ? base[(size_t)(2 * cp + 1) * S + g0] : 0.f;
            patchH[cp * CPS + pos0] = packh(v0, v1);
        }
        if (has1) {
#pragma unroll
            for (int cp = 0; cp < 8; cp++) {
                float v0 = va1 ? base[(size_t)(2 * cp) * S + g1] : 0.f;
                float v1 = va1 ? base[(size_t)(2 * cp + 1) * S + g1] : 0.f;
                patchH[cp * CPS + pos1] = packh(v0, v1);
            }
        }
        for (int i = tid; i < 576; i += 256) {
            int ln = i & 31, rest = i >> 5;
            int mt = rest & 1, khkw = rest >> 1;
            int llq = ln >> 2, llj = ln & 3;
            int co0 = cog * 32 + mt * 16 + llq;
            const float* wb = Wo + ((size_t)co0 * 96 + cig * 16) * 9 + khkw;
            uint4 f;
            f.x = packh(wb[(2 * llj) * 9],     wb[(2 * llj + 1) * 9]);
            f.y = packh(wb[864 * 8 + (2 * llj) * 9], wb[864 * 8 + (2 * llj + 1) * 9]);
            f.z = packh(wb[(2 * llj + 8) * 9], wb[(2 * llj + 9) * 9]);
            f.w = packh(wb[864 * 8 + (2 * llj + 8) * 9], wb[864 * 8 + (2 * llj + 9) * 9]);
            Wfrag[i] = f;
        }
        __syncthreads();

#pragma unroll
        for (int khkw = 0; khkw < 9; khkw++) {
            int kh = khkw / 3, kw = khkw % 3;
            uint4 a0 = Wfrag[(khkw * 2 + 0) * 32 + lane];
            uint4 a1 = Wfrag[(khkw * 2 + 1) * 32 + lane];
#pragma unroll
            for (int nt = 0; nt < 4; nt++) {
                int off = bbase[nt] + kh * 18 + kw;
                uint32_t b0 = rowA[off];
                uint32_t b1 = rowB[off];
                mma16816h(oacc[0][nt], (const uint32_t*)&a0, b0, b1);
                mma16816h(oacc[1][nt], (const uint32_t*)&a1, b0, b1);
            }
        }
    }

#pragma unroll
    for (int mt = 0; mt < 2; mt++) {
        int coA = cog * 32 + mt * 16 + lq;
        int coB = coA + 8;
        float bA = bo[coA], bB = bo[coB];
        size_t baseA = ((size_t)n * 192 + coA) * S;
        size_t baseB = ((size_t)n * 192 + coB) * S;
#pragma unroll
        for (int nt = 0; nt < 4; nt++) {
            int y = ty0 + 2 * w + (nt >> 1);
            int x = tx0 + (nt & 1) * 8 + 2 * l4;
            *(float2*)&out[baseA + y * WW + x] = make_float2(oacc[mt][nt][0] + bA, oacc[mt][nt][1] + bA);
            *(float2*)&out[baseB + y * WW + x] = make_float2(oacc[mt][nt][2] + bB, oacc[mt][nt][3] + bB);
        }
    }
}

// ---------------- gates (float4) ----------------
__global__ __launch_bounds__(256)
void gates_kernel(const float* __restrict__ conv, const float* __restrict__ m,
                  float* __restrict__ out) {
    int idx4 = blockIdx.x * 256 + threadIdx.x;
    int n = idx4 >> 16;
    int rem = (idx4 & 65535) * 4;
    size_t base = (size_t)n * 192 * S;
    float4 iv = *(const float4*)&conv[base + rem];
    float4 gv = *(const float4*)&conv[base + 64 * S + rem];
    float4 ov = *(const float4*)&conv[base + 128 * S + rem];
    float4 mi = *(const float4*)&m[(size_t)n * 64 * S + rem];
    float4 hn, mn;
    {
        float si = 1.0f / (1.0f + __expf(-iv.x)), gg = tanhf(gv.x), so = 1.0f / (1.0f + __expf(-ov.x));
        mn.x = si * gg + (1.0f - si) * mi.x; hn.x = so * mn.x;
        si = 1.0f / (1.0f + __expf(-iv.y)); gg = tanhf(gv.y); so = 1.0f / (1.0f + __expf(-ov.y));
        mn.y = si * gg + (1.0f - si) * mi.y; hn.y = so * mn.y;
        si = 1.0f / (1.0f + __expf(-iv.z)); gg = tanhf(gv.z); so = 1.0f / (1.0f + __expf(-ov.z));
        mn.z = si * gg + (1.0f - si) * mi.z; hn.z = so * mn.z;
        si = 1.0f / (1.0f + __expf(-iv.w)); gg = tanhf(gv.w); so = 1.0f / (1.0f + __expf(-ov.w));
        mn.w = si * gg + (1.0f - si) * mi.w; hn.w = so * mn.w;
    }
    size_t oidx = (size_t)n * 64 * S + rem;
    *(float4*)&out[oidx] = hn;
    *(float4*)&out[1048576 + oidx] = mn;
}

// ---------------- launch ----------------
extern "C" void kernel_launch(void* const* d_in, const int* in_sizes, int n_in,
                              void* d_out, int out_size) {
    const float* h  = (const float*)d_in[0];
    const float* m  = (const float*)d_in[1];
    const float* Wh = (const float*)d_in[2];
    const float* bh = (const float*)d_in[3];
    const float* Wm = (const float*)d_in[4];
    const float* bm = (const float*)d_in[5];
    const float* Wz = (const float*)d_in[6];
    const float* bz = (const float*)d_in[7];
    const float* Wo = (const float*)d_in[8];
    const float* bo = (const float*)d_in[9];
    float* out = (float*)d_out;

    float *pHqkv, *pMkv, *pZ2, *pZp, *pConv;
    cudaGetSymbolAddress((void**)&pHqkv, g_hqkv);
    cudaGetSymbolAddress((void**)&pMkv,  g_mkv);
    cudaGetSymbolAddress((void**)&pZ2,   g_Z2);
    cudaGetSymbolAddress((void**)&pZp,   g_Zp);
    cudaGetSymbolAddress((void**)&pConv, g_conv);

    projhm_kernel<<<dim3(32, 5, 4), 128>>>(h, Wh, bh, pHqkv, m, Wm, bm, pMkv);
    repack_kernel<<<dim3(64, 2, 4), 256>>>();
    attn_mma_kernel<<<dim3(32, 2, 4), 256>>>(pHqkv, pZ2);
    projz_kernel<<<dim3(64, 1, 4), 128>>>(pZ2, Wz, bz, pZp);
    conv_tc_kernel<<<dim3(16, 6, 4), 256>>>(pZp, h, Wo, bo, pConv);
    gates_kernel<<<1024, 256>>>(pConv, m, out);
}